// round 8
// baseline (speedup 1.0000x reference)
#include <cuda_runtime.h>
#include <math.h>

// ---------------------------------------------------------------------------
// Problem constants (fixed by setup_inputs):
//   B=128, T=512, n_in=2, n_rec = n_out = n_init = 512
// ---------------------------------------------------------------------------
#define BN   128
#define TT   512
#define NR   512
#define NIN  2
#define CL   8      // CTAs per cluster
#define BG   8      // batch rows per cluster (128 rows / 16 clusters)
#define COLS 64     // n_rec columns per CTA (512 / 8)
#define NTH  256
#define DTAU 0.2f

// Static device scratch (no allocation allowed).
__device__ float g_h[BN * NR];     // h exchange buffer (full state)
__device__ float g_v[BN * NR];     // v = r*h exchange buffer
__device__ float g_UzT[NR * NR];   // W_uz transposed: [k][j]
__device__ float g_UrT[NR * NR];
__device__ float g_UhT[NR * NR];
__device__ float g_WeT[NR * NR];   // W_enc transposed
__device__ float g_WdT[NR * NR];   // W_dec transposed

__device__ __forceinline__ void cluster_sync_all() {
    asm volatile("barrier.cluster.arrive.aligned;" ::: "memory");
    asm volatile("barrier.cluster.wait.aligned;" ::: "memory");
}

__device__ __forceinline__ float sigmoidf_(float x) {
    return 1.0f / (1.0f + expf(-x));
}

// ---------------------------------------------------------------------------
// Transpose all 5 weight matrices (512x512): dst[k][j] = src[j][k]
// grid (16,16,5), block (32,8)
// ---------------------------------------------------------------------------
__global__ void transpose_all(const float* __restrict__ W_uz,
                              const float* __restrict__ W_ur,
                              const float* __restrict__ W_uh,
                              const float* __restrict__ W_enc,
                              const float* __restrict__ W_dec) {
    __shared__ float tile[32][33];
    const float* src;
    float* dst;
    switch (blockIdx.z) {
        case 0: src = W_uz;  dst = g_UzT; break;
        case 1: src = W_ur;  dst = g_UrT; break;
        case 2: src = W_uh;  dst = g_UhT; break;
        case 3: src = W_enc; dst = g_WeT; break;
        default: src = W_dec; dst = g_WdT; break;
    }
    const int bx = blockIdx.x * 32, by = blockIdx.y * 32;
    const int tx = threadIdx.x, ty = threadIdx.y;
#pragma unroll
    for (int i = 0; i < 32; i += 8)
        tile[ty + i][tx] = src[(size_t)(by + ty + i) * NR + bx + tx];
    __syncthreads();
#pragma unroll
    for (int i = 0; i < 32; i += 8)
        dst[(size_t)(bx + ty + i) * NR + by + tx] = tile[tx][ty + i];
}

// ---------------------------------------------------------------------------
// Encoder: g_h[b][j] = sum_k init[b][k] * W_enc[j][k] = sum_k init[b][k]*WeT[k][j]
// grid (128, 4), 128 threads
// ---------------------------------------------------------------------------
__global__ void encoder_kernel(const float* __restrict__ init_state) {
    __shared__ float sI[NR];
    const int b = blockIdx.x;
    const int j = blockIdx.y * 128 + threadIdx.x;
    for (int i = threadIdx.x; i < NR; i += 128)
        sI[i] = init_state[(size_t)b * NR + i];
    __syncthreads();
    float acc = 0.0f;
#pragma unroll 8
    for (int k = 0; k < NR; k++)
        acc = fmaf(sI[k], g_WeT[(size_t)k * NR + j], acc);
    g_h[(size_t)b * NR + j] = acc;
}

// ---------------------------------------------------------------------------
// Persistent recurrent kernel.
// Grid = 128 CTAs = 16 independent clusters of 8. 256 threads/CTA.
// Cluster owns 8 batch rows; CTA owns 64 recurrent columns.
// ---------------------------------------------------------------------------
__global__ void __cluster_dims__(CL, 1, 1) __launch_bounds__(NTH, 1)
rnn_persistent(const float* __restrict__ x,
               const float* __restrict__ W_wz,
               const float* __restrict__ W_wr,
               const float* __restrict__ W_wh,
               float* __restrict__ out_h)
{
    __shared__ float sH[BG][NR];                 // full h (phase1) / full v (phase2)
    __shared__ float sRed[2][4][BG][COLS];       // K-chunk partial sums
    __shared__ float sZ[BG][COLS];               // z gate (own slice)
    __shared__ float sHown[BG][COLS];            // old h (own slice)
    __shared__ float sWin[3][COLS][NIN];         // input-proj weight slices
    __shared__ float sX[BG][NIN];                // x_t for the 8 rows

    const int tid     = threadIdx.x;
    const int cta     = blockIdx.x;
    const int cl      = cta / CL;
    const int rank    = cta % CL;
    const int b0      = cl * BG;
    const int colbase = rank * COLS;

    // Thread tile for the GEMM phases:
    const int kc    = tid >> 6;           // 0..3  (K chunk of 128)
    const int r6    = tid & 63;
    const int j0    = (r6 & 15) << 2;     // 0,4,...,60
    const int brow  = (r6 >> 4) << 1;     // 0,2,4,6 (2 rows)
    const int kbase = kc << 7;

    // Load input-projection weight slices (n_in = 2).
    if (tid < COLS) {
        const int j = colbase + tid;
        sWin[0][tid][0] = W_wz[j * NIN + 0];
        sWin[0][tid][1] = W_wz[j * NIN + 1];
        sWin[1][tid][0] = W_wr[j * NIN + 0];
        sWin[1][tid][1] = W_wr[j * NIN + 1];
        sWin[2][tid][0] = W_wh[j * NIN + 0];
        sWin[2][tid][1] = W_wh[j * NIN + 1];
    }

    // Load h0 (written by encoder_kernel) into sH.
    {
        const float4* src = reinterpret_cast<const float4*>(g_h + (size_t)b0 * NR);
        float4* dst = reinterpret_cast<float4*>(&sH[0][0]);
        for (int i = tid; i < BG * NR / 4; i += NTH)
            dst[i] = __ldcv(src + i);
    }
    __syncthreads();

    const float* __restrict__ wzBase = g_UzT + colbase + j0;
    const float* __restrict__ wrBase = g_UrT + colbase + j0;
    const float* __restrict__ whBase = g_UhT + colbase + j0;

    for (int t = 0; t < TT; t++) {
        // Load x_t for our 8 rows.
        if (tid < BG * NIN) {
            const int b = tid >> 1, c = tid & 1;
            sX[b][c] = x[((size_t)(b0 + b) * TT + t) * NIN + c];
        }

        // ---------------- Phase 1: z, r gate GEMMs ----------------
        {
            float az[2][4] = {{0,0,0,0},{0,0,0,0}};
            float ar[2][4] = {{0,0,0,0},{0,0,0,0}};
            const float* wz = wzBase + (size_t)kbase * NR;
            const float* wr = wrBase + (size_t)kbase * NR;
            const float* hr0 = &sH[brow][kbase];
            const float* hr1 = &sH[brow + 1][kbase];
#pragma unroll 4
            for (int k = 0; k < 128; k++) {
                const float h0v = hr0[k];
                const float h1v = hr1[k];
                const float4 wzv = *reinterpret_cast<const float4*>(wz + (size_t)k * NR);
                const float4 wrv = *reinterpret_cast<const float4*>(wr + (size_t)k * NR);
                az[0][0] = fmaf(h0v, wzv.x, az[0][0]);
                az[0][1] = fmaf(h0v, wzv.y, az[0][1]);
                az[0][2] = fmaf(h0v, wzv.z, az[0][2]);
                az[0][3] = fmaf(h0v, wzv.w, az[0][3]);
                az[1][0] = fmaf(h1v, wzv.x, az[1][0]);
                az[1][1] = fmaf(h1v, wzv.y, az[1][1]);
                az[1][2] = fmaf(h1v, wzv.z, az[1][2]);
                az[1][3] = fmaf(h1v, wzv.w, az[1][3]);
                ar[0][0] = fmaf(h0v, wrv.x, ar[0][0]);
                ar[0][1] = fmaf(h0v, wrv.y, ar[0][1]);
                ar[0][2] = fmaf(h0v, wrv.z, ar[0][2]);
                ar[0][3] = fmaf(h0v, wrv.w, ar[0][3]);
                ar[1][0] = fmaf(h1v, wrv.x, ar[1][0]);
                ar[1][1] = fmaf(h1v, wrv.y, ar[1][1]);
                ar[1][2] = fmaf(h1v, wrv.z, ar[1][2]);
                ar[1][3] = fmaf(h1v, wrv.w, ar[1][3]);
            }
#pragma unroll
            for (int bb = 0; bb < 2; bb++) {
                *reinterpret_cast<float4*>(&sRed[0][kc][brow + bb][j0]) =
                    make_float4(az[bb][0], az[bb][1], az[bb][2], az[bb][3]);
                *reinterpret_cast<float4*>(&sRed[1][kc][brow + bb][j0]) =
                    make_float4(ar[bb][0], ar[bb][1], ar[bb][2], ar[bb][3]);
            }
        }
        __syncthreads();

        // Phase 1 epilogue: reduce chunks, gates, v = r*h (own slice -> g_v).
        for (int idx = tid; idx < BG * COLS; idx += NTH) {
            const int b = idx >> 6, j = idx & 63;
            const float sz = sRed[0][0][b][j] + sRed[0][1][b][j]
                           + sRed[0][2][b][j] + sRed[0][3][b][j];
            const float sr = sRed[1][0][b][j] + sRed[1][1][b][j]
                           + sRed[1][2][b][j] + sRed[1][3][b][j];
            const float xz = sX[b][0] * sWin[0][j][0] + sX[b][1] * sWin[0][j][1];
            const float xr = sX[b][0] * sWin[1][j][0] + sX[b][1] * sWin[1][j][1];
            const float z  = sigmoidf_(xz + sz);
            const float r  = sigmoidf_(xr + sr);
            const float hc = sH[b][colbase + j];
            sZ[b][j]    = z;
            sHown[b][j] = hc;
            g_v[(size_t)(b0 + b) * NR + colbase + j] = r * hc;
        }
        cluster_sync_all();   // all v slices visible cluster-wide

        // Refill sH with full v.
        {
            const float4* src = reinterpret_cast<const float4*>(g_v + (size_t)b0 * NR);
            float4* dst = reinterpret_cast<float4*>(&sH[0][0]);
            for (int i = tid; i < BG * NR / 4; i += NTH)
                dst[i] = __ldcv(src + i);
        }
        __syncthreads();

        // ---------------- Phase 2: candidate GEMM (v @ Uh^T) ----------------
        {
            float au[2][4] = {{0,0,0,0},{0,0,0,0}};
            const float* wh = whBase + (size_t)kbase * NR;
            const float* vr0 = &sH[brow][kbase];
            const float* vr1 = &sH[brow + 1][kbase];
#pragma unroll 4
            for (int k = 0; k < 128; k++) {
                const float v0 = vr0[k];
                const float v1 = vr1[k];
                const float4 wv = *reinterpret_cast<const float4*>(wh + (size_t)k * NR);
                au[0][0] = fmaf(v0, wv.x, au[0][0]);
                au[0][1] = fmaf(v0, wv.y, au[0][1]);
                au[0][2] = fmaf(v0, wv.z, au[0][2]);
                au[0][3] = fmaf(v0, wv.w, au[0][3]);
                au[1][0] = fmaf(v1, wv.x, au[1][0]);
                au[1][1] = fmaf(v1, wv.y, au[1][1]);
                au[1][2] = fmaf(v1, wv.z, au[1][2]);
                au[1][3] = fmaf(v1, wv.w, au[1][3]);
            }
#pragma unroll
            for (int bb = 0; bb < 2; bb++)
                *reinterpret_cast<float4*>(&sRed[0][kc][brow + bb][j0]) =
                    make_float4(au[bb][0], au[bb][1], au[bb][2], au[bb][3]);
        }
        __syncthreads();

        // Phase 2 epilogue: u, tanh, leaky update; write h_t to output + g_h.
        for (int idx = tid; idx < BG * COLS; idx += NTH) {
            const int b = idx >> 6, j = idx & 63;
            const float su = sRed[0][0][b][j] + sRed[0][1][b][j]
                           + sRed[0][2][b][j] + sRed[0][3][b][j];
            const float xh = sX[b][0] * sWin[2][j][0] + sX[b][1] * sWin[2][j][1];
            const float u  = xh + su;
            const float hc = sHown[b][j];
            const float z  = sZ[b][j];
            const float hn = hc + DTAU * (z - 1.0f) * (hc - tanhf(u));
            out_h[((size_t)(b0 + b) * TT + t) * NR + colbase + j] = hn;
            g_h[(size_t)(b0 + b) * NR + colbase + j] = hn;
        }
        cluster_sync_all();   // all new-h slices visible cluster-wide

        // Refill sH with full new h for next step.
        {
            const float4* src = reinterpret_cast<const float4*>(g_h + (size_t)b0 * NR);
            float4* dst = reinterpret_cast<float4*>(&sH[0][0]);
            for (int i = tid; i < BG * NR / 4; i += NTH)
                dst[i] = __ldcv(src + i);
        }
        __syncthreads();
    }
}

// ---------------------------------------------------------------------------
// Decoder GEMM: y[bt][o] = sum_r h[bt][r] * W_dec[o][r]
//             = A (65536 x 512) * g_WdT (512 x 512)
// 128x128 block tile, K-tile 8, 8x8 thread tile (2x2 quadrants of 4).
// grid (4, 512), 256 threads.
// ---------------------------------------------------------------------------
__global__ void __launch_bounds__(256)
decoder_gemm(const float* __restrict__ A, float* __restrict__ C) {
    __shared__ float As[8][128];
    __shared__ float Bs[8][128];

    const int tid = threadIdx.x;
    const int tx = tid & 15;       // 16
    const int ty = tid >> 4;       // 16
    const int m0 = blockIdx.y * 128;
    const int n0 = blockIdx.x * 128;

    float acc[8][8];
#pragma unroll
    for (int i = 0; i < 8; i++)
#pragma unroll
        for (int j = 0; j < 8; j++) acc[i][j] = 0.0f;

    const int lrow = tid >> 1;          // 0..127
    const int lk   = (tid & 1) << 2;    // 0 or 4
    const int brow = tid >> 5;          // 0..7
    const int bcol = (tid & 31) << 2;   // 0..124

    for (int k0 = 0; k0 < NR; k0 += 8) {
        const float4 av = *reinterpret_cast<const float4*>(
            A + (size_t)(m0 + lrow) * NR + k0 + lk);
        As[lk + 0][lrow] = av.x;
        As[lk + 1][lrow] = av.y;
        As[lk + 2][lrow] = av.z;
        As[lk + 3][lrow] = av.w;
        *reinterpret_cast<float4*>(&Bs[brow][bcol]) =
            *reinterpret_cast<const float4*>(
                g_WdT + (size_t)(k0 + brow) * NR + n0 + bcol);
        __syncthreads();

#pragma unroll
        for (int kk = 0; kk < 8; kk++) {
            float a[8], b[8];
            *reinterpret_cast<float4*>(a)     = *reinterpret_cast<const float4*>(&As[kk][ty * 4]);
            *reinterpret_cast<float4*>(a + 4) = *reinterpret_cast<const float4*>(&As[kk][64 + ty * 4]);
            *reinterpret_cast<float4*>(b)     = *reinterpret_cast<const float4*>(&Bs[kk][tx * 4]);
            *reinterpret_cast<float4*>(b + 4) = *reinterpret_cast<const float4*>(&Bs[kk][64 + tx * 4]);
#pragma unroll
            for (int i = 0; i < 8; i++)
#pragma unroll
                for (int j = 0; j < 8; j++)
                    acc[i][j] = fmaf(a[i], b[j], acc[i][j]);
        }
        __syncthreads();
    }

#pragma unroll
    for (int ri = 0; ri < 2; ri++) {
#pragma unroll
        for (int i = 0; i < 4; i++) {
            const int row = m0 + ri * 64 + ty * 4 + i;
            const int ii = ri * 4 + i;
            *reinterpret_cast<float4*>(C + (size_t)row * NR + n0 + tx * 4) =
                make_float4(acc[ii][0], acc[ii][1], acc[ii][2], acc[ii][3]);
            *reinterpret_cast<float4*>(C + (size_t)row * NR + n0 + 64 + tx * 4) =
                make_float4(acc[ii][4], acc[ii][5], acc[ii][6], acc[ii][7]);
        }
    }
}

// ---------------------------------------------------------------------------
// Launch. Inputs (metadata order): x, init_state, W_enc, W_wz, W_uz, W_wr,
// W_ur, W_wh, W_uh, W_dec. Output: [h_1t | y_1t] concatenated,
// each (B, T, NR) fp32.
// ---------------------------------------------------------------------------
extern "C" void kernel_launch(void* const* d_in, const int* in_sizes, int n_in,
                              void* d_out, int out_size) {
    const float* x     = (const float*)d_in[0];
    const float* init  = (const float*)d_in[1];
    const float* W_enc = (const float*)d_in[2];
    const float* W_wz  = (const float*)d_in[3];
    const float* W_uz  = (const float*)d_in[4];
    const float* W_wr  = (const float*)d_in[5];
    const float* W_ur  = (const float*)d_in[6];
    const float* W_wh  = (const float*)d_in[7];
    const float* W_uh  = (const float*)d_in[8];
    const float* W_dec = (const float*)d_in[9];

    float* out_h = (float*)d_out;
    float* out_y = out_h + (size_t)BN * TT * NR;

    transpose_all<<<dim3(16, 16, 5), dim3(32, 8)>>>(W_uz, W_ur, W_uh, W_enc, W_dec);
    encoder_kernel<<<dim3(BN, 4), 128>>>(init);
    rnn_persistent<<<BN, NTH>>>(x, W_wz, W_wr, W_wh, out_h);
    decoder_gemm<<<dim3(4, 512), 256>>>(out_h, out_y);
}

// round 9
// speedup vs baseline: 1.0516x; 1.0516x over previous
#include <cuda_runtime.h>
#include <math.h>

// ---------------------------------------------------------------------------
// Problem constants (fixed by setup_inputs):
//   B=128, T=512, n_in=2, n_rec = n_out = n_init = 512
// ---------------------------------------------------------------------------
#define BN   128
#define TT   512
#define NR   512
#define NIN  2
#define CL   8      // CTAs per cluster
#define BG   8      // batch rows per cluster (128 rows / 16 clusters)
#define COLS 64     // n_rec columns per CTA (512 / 8)
#define NTH  512    // threads per CTA (16 warps)
#define NKC  16     // K chunks (32 k each)
#define SHP  (NR + 4)   // padded sH row pitch (kills LDS bank conflicts)
#define DTAU 0.2f

// Dynamic smem layout (floats):
//   sH    [BG][SHP]             4128
//   sRed  [2][NKC][BG][COLS]   16384
//   sZ    [BG][COLS]             512
//   sHown [BG][COLS]             512
//   sWin  [3][COLS][NIN]         384
//   sX    [BG][NIN]               16
#define SM_FLOATS (BG*SHP + 2*NKC*BG*COLS + BG*COLS + BG*COLS + 3*COLS*NIN + BG*NIN)
#define SM_BYTES  (SM_FLOATS * 4)

// Static device scratch (no allocation allowed).
__device__ float g_h[BN * NR];     // h exchange buffer (full state)
__device__ float g_v[BN * NR];     // v = r*h exchange buffer
__device__ float g_UzT[NR * NR];   // W_uz transposed: [k][j]
__device__ float g_UrT[NR * NR];
__device__ float g_UhT[NR * NR];
__device__ float g_WeT[NR * NR];   // W_enc transposed
__device__ float g_WdT[NR * NR];   // W_dec transposed

__device__ __forceinline__ void cluster_sync_all() {
    asm volatile("barrier.cluster.arrive.aligned;" ::: "memory");
    asm volatile("barrier.cluster.wait.aligned;" ::: "memory");
}

__device__ __forceinline__ float sigmoidf_(float x) {
    return 1.0f / (1.0f + expf(-x));
}

// ---------------------------------------------------------------------------
// Transpose all 5 weight matrices (512x512): dst[k][j] = src[j][k]
// grid (16,16,5), block (32,8)
// ---------------------------------------------------------------------------
__global__ void transpose_all(const float* __restrict__ W_uz,
                              const float* __restrict__ W_ur,
                              const float* __restrict__ W_uh,
                              const float* __restrict__ W_enc,
                              const float* __restrict__ W_dec) {
    __shared__ float tile[32][33];
    const float* src;
    float* dst;
    switch (blockIdx.z) {
        case 0: src = W_uz;  dst = g_UzT; break;
        case 1: src = W_ur;  dst = g_UrT; break;
        case 2: src = W_uh;  dst = g_UhT; break;
        case 3: src = W_enc; dst = g_WeT; break;
        default: src = W_dec; dst = g_WdT; break;
    }
    const int bx = blockIdx.x * 32, by = blockIdx.y * 32;
    const int tx = threadIdx.x, ty = threadIdx.y;
#pragma unroll
    for (int i = 0; i < 32; i += 8)
        tile[ty + i][tx] = src[(size_t)(by + ty + i) * NR + bx + tx];
    __syncthreads();
#pragma unroll
    for (int i = 0; i < 32; i += 8)
        dst[(size_t)(bx + ty + i) * NR + by + tx] = tile[tx][ty + i];
}

// ---------------------------------------------------------------------------
// Encoder: g_h[b][j] = sum_k init[b][k] * WeT[k][j]
// grid (128, 4), 128 threads
// ---------------------------------------------------------------------------
__global__ void encoder_kernel(const float* __restrict__ init_state) {
    __shared__ float sI[NR];
    const int b = blockIdx.x;
    const int j = blockIdx.y * 128 + threadIdx.x;
    for (int i = threadIdx.x; i < NR; i += 128)
        sI[i] = init_state[(size_t)b * NR + i];
    __syncthreads();
    float acc = 0.0f;
#pragma unroll 8
    for (int k = 0; k < NR; k++)
        acc = fmaf(sI[k], g_WeT[(size_t)k * NR + j], acc);
    g_h[(size_t)b * NR + j] = acc;
}

// ---------------------------------------------------------------------------
// Persistent recurrent kernel.
// Grid = 128 CTAs = 16 independent clusters of 8. 512 threads/CTA.
// Cluster owns 8 batch rows; CTA owns 64 recurrent columns.
// GEMM thread tile: 4 rows x 4 cols, K split into 16 chunks of 32.
// ---------------------------------------------------------------------------
__global__ void __cluster_dims__(CL, 1, 1) __launch_bounds__(NTH, 1)
rnn_persistent(const float* __restrict__ x,
               const float* __restrict__ W_wz,
               const float* __restrict__ W_wr,
               const float* __restrict__ W_wh,
               float* __restrict__ out_h)
{
    extern __shared__ float dynsm[];
    float (*sH)[SHP]              = (float (*)[SHP])dynsm;
    float* p = dynsm + BG * SHP;
    float (*sRed)[NKC][BG][COLS]  = (float (*)[NKC][BG][COLS])p;  p += 2 * NKC * BG * COLS;
    float (*sZ)[COLS]             = (float (*)[COLS])p;           p += BG * COLS;
    float (*sHown)[COLS]          = (float (*)[COLS])p;           p += BG * COLS;
    float (*sWin)[COLS][NIN]      = (float (*)[COLS][NIN])p;      p += 3 * COLS * NIN;
    float (*sX)[NIN]              = (float (*)[NIN])p;

    const int tid     = threadIdx.x;
    const int cta     = blockIdx.x;
    const int cl      = cta / CL;
    const int rank    = cta % CL;
    const int b0      = cl * BG;
    const int colbase = rank * COLS;

    // GEMM thread mapping: warp = one K chunk; lanes span (rowgroup, colgroup).
    const int kc = tid >> 5;              // 0..15
    const int r5 = tid & 31;
    const int j0 = (r5 & 15) << 2;        // 0,4,...,60
    const int rg = (r5 >> 4) << 2;        // 0 or 4 (row base, 4 rows)
    const int kb = kc << 5;               // K chunk base (32 wide)

    // Epilogue mapping: one output element per thread (512 = 8*64).
    const int eb = tid >> 6;              // batch row 0..7
    const int ej = tid & 63;              // column 0..63

    // Load input-projection weight slices (n_in = 2).
    if (tid < COLS) {
        const int j = colbase + tid;
        sWin[0][tid][0] = W_wz[j * NIN + 0];
        sWin[0][tid][1] = W_wz[j * NIN + 1];
        sWin[1][tid][0] = W_wr[j * NIN + 0];
        sWin[1][tid][1] = W_wr[j * NIN + 1];
        sWin[2][tid][0] = W_wh[j * NIN + 0];
        sWin[2][tid][1] = W_wh[j * NIN + 1];
    }

    // Load h0 (written by encoder_kernel) into sH.
    {
        for (int i = tid; i < BG * (NR / 4); i += NTH) {
            const int b = i >> 7, idx = i & 127;
            reinterpret_cast<float4*>(&sH[b][0])[idx] =
                __ldcv(reinterpret_cast<const float4*>(g_h + (size_t)(b0 + b) * NR) + idx);
        }
    }
    __syncthreads();

    const float* __restrict__ wzBase = g_UzT + (size_t)kb * NR + colbase + j0;
    const float* __restrict__ wrBase = g_UrT + (size_t)kb * NR + colbase + j0;
    const float* __restrict__ whBase = g_UhT + (size_t)kb * NR + colbase + j0;

    for (int t = 0; t < TT; t++) {
        // Load x_t for our 8 rows.
        if (tid < BG * NIN) {
            const int b = tid >> 1, c = tid & 1;
            sX[b][c] = x[((size_t)(b0 + b) * TT + t) * NIN + c];
        }

        // ---------------- Phase 1: z, r gate GEMMs ----------------
        {
            float az[4][4] = {{0,0,0,0},{0,0,0,0},{0,0,0,0},{0,0,0,0}};
            float ar[4][4] = {{0,0,0,0},{0,0,0,0},{0,0,0,0},{0,0,0,0}};
            const float* __restrict__ h0p = &sH[rg + 0][kb];
            const float* __restrict__ h1p = &sH[rg + 1][kb];
            const float* __restrict__ h2p = &sH[rg + 2][kb];
            const float* __restrict__ h3p = &sH[rg + 3][kb];
#pragma unroll 8
            for (int k = 0; k < 32; k++) {
                const float4 wzv = *reinterpret_cast<const float4*>(wzBase + (size_t)k * NR);
                const float4 wrv = *reinterpret_cast<const float4*>(wrBase + (size_t)k * NR);
                const float hv0 = h0p[k], hv1 = h1p[k], hv2 = h2p[k], hv3 = h3p[k];
                az[0][0] = fmaf(hv0, wzv.x, az[0][0]); az[0][1] = fmaf(hv0, wzv.y, az[0][1]);
                az[0][2] = fmaf(hv0, wzv.z, az[0][2]); az[0][3] = fmaf(hv0, wzv.w, az[0][3]);
                az[1][0] = fmaf(hv1, wzv.x, az[1][0]); az[1][1] = fmaf(hv1, wzv.y, az[1][1]);
                az[1][2] = fmaf(hv1, wzv.z, az[1][2]); az[1][3] = fmaf(hv1, wzv.w, az[1][3]);
                az[2][0] = fmaf(hv2, wzv.x, az[2][0]); az[2][1] = fmaf(hv2, wzv.y, az[2][1]);
                az[2][2] = fmaf(hv2, wzv.z, az[2][2]); az[2][3] = fmaf(hv2, wzv.w, az[2][3]);
                az[3][0] = fmaf(hv3, wzv.x, az[3][0]); az[3][1] = fmaf(hv3, wzv.y, az[3][1]);
                az[3][2] = fmaf(hv3, wzv.z, az[3][2]); az[3][3] = fmaf(hv3, wzv.w, az[3][3]);
                ar[0][0] = fmaf(hv0, wrv.x, ar[0][0]); ar[0][1] = fmaf(hv0, wrv.y, ar[0][1]);
                ar[0][2] = fmaf(hv0, wrv.z, ar[0][2]); ar[0][3] = fmaf(hv0, wrv.w, ar[0][3]);
                ar[1][0] = fmaf(hv1, wrv.x, ar[1][0]); ar[1][1] = fmaf(hv1, wrv.y, ar[1][1]);
                ar[1][2] = fmaf(hv1, wrv.z, ar[1][2]); ar[1][3] = fmaf(hv1, wrv.w, ar[1][3]);
                ar[2][0] = fmaf(hv2, wrv.x, ar[2][0]); ar[2][1] = fmaf(hv2, wrv.y, ar[2][1]);
                ar[2][2] = fmaf(hv2, wrv.z, ar[2][2]); ar[2][3] = fmaf(hv2, wrv.w, ar[2][3]);
                ar[3][0] = fmaf(hv3, wrv.x, ar[3][0]); ar[3][1] = fmaf(hv3, wrv.y, ar[3][1]);
                ar[3][2] = fmaf(hv3, wrv.z, ar[3][2]); ar[3][3] = fmaf(hv3, wrv.w, ar[3][3]);
            }
#pragma unroll
            for (int b = 0; b < 4; b++) {
                *reinterpret_cast<float4*>(&sRed[0][kc][rg + b][j0]) =
                    make_float4(az[b][0], az[b][1], az[b][2], az[b][3]);
                *reinterpret_cast<float4*>(&sRed[1][kc][rg + b][j0]) =
                    make_float4(ar[b][0], ar[b][1], ar[b][2], ar[b][3]);
            }
        }
        __syncthreads();

        // Phase 1 epilogue: reduce chunks, gates, v = r*h (own slice -> g_v).
        {
            float sz = 0.0f, sr = 0.0f;
#pragma unroll
            for (int c = 0; c < NKC; c++) {
                sz += sRed[0][c][eb][ej];
                sr += sRed[1][c][eb][ej];
            }
            const float xz = sX[eb][0] * sWin[0][ej][0] + sX[eb][1] * sWin[0][ej][1];
            const float xr = sX[eb][0] * sWin[1][ej][0] + sX[eb][1] * sWin[1][ej][1];
            const float z  = sigmoidf_(xz + sz);
            const float r  = sigmoidf_(xr + sr);
            const float hc = sH[eb][colbase + ej];
            sZ[eb][ej]    = z;
            sHown[eb][ej] = hc;
            g_v[(size_t)(b0 + eb) * NR + colbase + ej] = r * hc;
        }
        cluster_sync_all();   // all v slices visible cluster-wide

        // Refill sH with full v.
        for (int i = tid; i < BG * (NR / 4); i += NTH) {
            const int b = i >> 7, idx = i & 127;
            reinterpret_cast<float4*>(&sH[b][0])[idx] =
                __ldcv(reinterpret_cast<const float4*>(g_v + (size_t)(b0 + b) * NR) + idx);
        }
        __syncthreads();

        // ---------------- Phase 2: candidate GEMM (v @ Uh^T) ----------------
        {
            float au[4][4] = {{0,0,0,0},{0,0,0,0},{0,0,0,0},{0,0,0,0}};
            const float* __restrict__ v0p = &sH[rg + 0][kb];
            const float* __restrict__ v1p = &sH[rg + 1][kb];
            const float* __restrict__ v2p = &sH[rg + 2][kb];
            const float* __restrict__ v3p = &sH[rg + 3][kb];
#pragma unroll 8
            for (int k = 0; k < 32; k++) {
                const float4 wv = *reinterpret_cast<const float4*>(whBase + (size_t)k * NR);
                const float v0 = v0p[k], v1 = v1p[k], v2 = v2p[k], v3 = v3p[k];
                au[0][0] = fmaf(v0, wv.x, au[0][0]); au[0][1] = fmaf(v0, wv.y, au[0][1]);
                au[0][2] = fmaf(v0, wv.z, au[0][2]); au[0][3] = fmaf(v0, wv.w, au[0][3]);
                au[1][0] = fmaf(v1, wv.x, au[1][0]); au[1][1] = fmaf(v1, wv.y, au[1][1]);
                au[1][2] = fmaf(v1, wv.z, au[1][2]); au[1][3] = fmaf(v1, wv.w, au[1][3]);
                au[2][0] = fmaf(v2, wv.x, au[2][0]); au[2][1] = fmaf(v2, wv.y, au[2][1]);
                au[2][2] = fmaf(v2, wv.z, au[2][2]); au[2][3] = fmaf(v2, wv.w, au[2][3]);
                au[3][0] = fmaf(v3, wv.x, au[3][0]); au[3][1] = fmaf(v3, wv.y, au[3][1]);
                au[3][2] = fmaf(v3, wv.z, au[3][2]); au[3][3] = fmaf(v3, wv.w, au[3][3]);
            }
#pragma unroll
            for (int b = 0; b < 4; b++)
                *reinterpret_cast<float4*>(&sRed[0][kc][rg + b][j0]) =
                    make_float4(au[b][0], au[b][1], au[b][2], au[b][3]);
        }
        __syncthreads();

        // Phase 2 epilogue: u, tanh, leaky update; write h_t to output + g_h.
        {
            float su = 0.0f;
#pragma unroll
            for (int c = 0; c < NKC; c++)
                su += sRed[0][c][eb][ej];
            const float xh = sX[eb][0] * sWin[2][ej][0] + sX[eb][1] * sWin[2][ej][1];
            const float u  = xh + su;
            const float hc = sHown[eb][ej];
            const float z  = sZ[eb][ej];
            const float hn = hc + DTAU * (z - 1.0f) * (hc - tanhf(u));
            out_h[((size_t)(b0 + eb) * TT + t) * NR + colbase + ej] = hn;
            g_h[(size_t)(b0 + eb) * NR + colbase + ej] = hn;
        }
        cluster_sync_all();   // all new-h slices visible cluster-wide

        // Refill sH with full new h for next step.
        for (int i = tid; i < BG * (NR / 4); i += NTH) {
            const int b = i >> 7, idx = i & 127;
            reinterpret_cast<float4*>(&sH[b][0])[idx] =
                __ldcv(reinterpret_cast<const float4*>(g_h + (size_t)(b0 + b) * NR) + idx);
        }
        __syncthreads();
    }
}

// ---------------------------------------------------------------------------
// Decoder GEMM: y[bt][o] = sum_r h[bt][r] * W_dec[o][r]
//             = A (65536 x 512) * g_WdT (512 x 512)
// 128x128 block tile, K-tile 8, 8x8 thread tile (2x2 quadrants of 4).
// grid (4, 512), 256 threads.
// ---------------------------------------------------------------------------
__global__ void __launch_bounds__(256)
decoder_gemm(const float* __restrict__ A, float* __restrict__ C) {
    __shared__ float As[8][128];
    __shared__ float Bs[8][128];

    const int tid = threadIdx.x;
    const int tx = tid & 15;       // 16
    const int ty = tid >> 4;       // 16
    const int m0 = blockIdx.y * 128;
    const int n0 = blockIdx.x * 128;

    float acc[8][8];
#pragma unroll
    for (int i = 0; i < 8; i++)
#pragma unroll
        for (int j = 0; j < 8; j++) acc[i][j] = 0.0f;

    const int lrow = tid >> 1;          // 0..127
    const int lk   = (tid & 1) << 2;    // 0 or 4
    const int brow = tid >> 5;          // 0..7
    const int bcol = (tid & 31) << 2;   // 0..124

    for (int k0 = 0; k0 < NR; k0 += 8) {
        const float4 av = *reinterpret_cast<const float4*>(
            A + (size_t)(m0 + lrow) * NR + k0 + lk);
        As[lk + 0][lrow] = av.x;
        As[lk + 1][lrow] = av.y;
        As[lk + 2][lrow] = av.z;
        As[lk + 3][lrow] = av.w;
        *reinterpret_cast<float4*>(&Bs[brow][bcol]) =
            *reinterpret_cast<const float4*>(
                g_WdT + (size_t)(k0 + brow) * NR + n0 + bcol);
        __syncthreads();

#pragma unroll
        for (int kk = 0; kk < 8; kk++) {
            float a[8], b[8];
            *reinterpret_cast<float4*>(a)     = *reinterpret_cast<const float4*>(&As[kk][ty * 4]);
            *reinterpret_cast<float4*>(a + 4) = *reinterpret_cast<const float4*>(&As[kk][64 + ty * 4]);
            *reinterpret_cast<float4*>(b)     = *reinterpret_cast<const float4*>(&Bs[kk][tx * 4]);
            *reinterpret_cast<float4*>(b + 4) = *reinterpret_cast<const float4*>(&Bs[kk][64 + tx * 4]);
#pragma unroll
            for (int i = 0; i < 8; i++)
#pragma unroll
                for (int j = 0; j < 8; j++)
                    acc[i][j] = fmaf(a[i], b[j], acc[i][j]);
        }
        __syncthreads();
    }

#pragma unroll
    for (int ri = 0; ri < 2; ri++) {
#pragma unroll
        for (int i = 0; i < 4; i++) {
            const int row = m0 + ri * 64 + ty * 4 + i;
            const int ii = ri * 4 + i;
            *reinterpret_cast<float4*>(C + (size_t)row * NR + n0 + tx * 4) =
                make_float4(acc[ii][0], acc[ii][1], acc[ii][2], acc[ii][3]);
            *reinterpret_cast<float4*>(C + (size_t)row * NR + n0 + 64 + tx * 4) =
                make_float4(acc[ii][4], acc[ii][5], acc[ii][6], acc[ii][7]);
        }
    }
}

// ---------------------------------------------------------------------------
// Launch. Inputs (metadata order): x, init_state, W_enc, W_wz, W_uz, W_wr,
// W_ur, W_wh, W_uh, W_dec. Output: [h_1t | y_1t] concatenated,
// each (B, T, NR) fp32.
// ---------------------------------------------------------------------------
extern "C" void kernel_launch(void* const* d_in, const int* in_sizes, int n_in,
                              void* d_out, int out_size) {
    const float* x     = (const float*)d_in[0];
    const float* init  = (const float*)d_in[1];
    const float* W_enc = (const float*)d_in[2];
    const float* W_wz  = (const float*)d_in[3];
    const float* W_uz  = (const float*)d_in[4];
    const float* W_wr  = (const float*)d_in[5];
    const float* W_ur  = (const float*)d_in[6];
    const float* W_wh  = (const float*)d_in[7];
    const float* W_uh  = (const float*)d_in[8];
    const float* W_dec = (const float*)d_in[9];

    float* out_h = (float*)d_out;
    float* out_y = out_h + (size_t)BN * TT * NR;

    cudaFuncSetAttribute(rnn_persistent,
                         cudaFuncAttributeMaxDynamicSharedMemorySize, SM_BYTES);

    transpose_all<<<dim3(16, 16, 5), dim3(32, 8)>>>(W_uz, W_ur, W_uh, W_enc, W_dec);
    encoder_kernel<<<dim3(BN, 4), 128>>>(init);
    rnn_persistent<<<BN, NTH, SM_BYTES>>>(x, W_wz, W_wr, W_wh, out_h);
    decoder_gemm<<<dim3(4, 512), 256>>>(out_h, out_y);
}

// round 11
// speedup vs baseline: 1.0529x; 1.0012x over previous
#include <cuda_runtime.h>
#include <math.h>

// ---------------------------------------------------------------------------
// Problem constants (fixed by setup_inputs):
//   B=128, T=512, n_in=2, n_rec = n_out = n_init = 512
// ---------------------------------------------------------------------------
#define BN   128
#define TT   512
#define NR   512
#define NIN  2
#define CL   8      // CTAs per cluster
#define BG   8      // batch rows per cluster (128 rows / 16 clusters)
#define COLS 64     // n_rec columns per CTA (512 / 8)
#define NTH  512    // threads per CTA (16 warps)
#define NKC  16     // K chunks (32 k each)
#define SHP  (NR + 4)   // padded sH row pitch (kills LDS bank conflicts)
#define DTAU 0.2f

// Dynamic smem layout (floats):
//   sH    [BG][SHP]             4128
//   sRed  [2][NKC][BG][COLS]   16384
//   sZ    [BG][COLS]             512
//   sHown [BG][COLS]             512
//   sWin  [3][COLS][NIN]         384
//   sX    [BG][NIN]               16
#define SM_FLOATS (BG*SHP + 2*NKC*BG*COLS + BG*COLS + BG*COLS + 3*COLS*NIN + BG*NIN)
#define SM_BYTES  (SM_FLOATS * 4)

// Static device scratch (no allocation allowed).
__device__ float g_h[BN * NR];     // h exchange buffer (full state)
__device__ float g_v[BN * NR];     // v = r*h exchange buffer
__device__ float g_UzT[NR * NR];   // W_uz transposed: [k][j]
__device__ float g_UrT[NR * NR];
__device__ float g_UhT[NR * NR];
__device__ float g_WeT[NR * NR];   // W_enc transposed
__device__ float g_WdT[NR * NR];   // W_dec transposed

__device__ __forceinline__ void cluster_sync_all() {
    asm volatile("barrier.cluster.arrive.aligned;" ::: "memory");
    asm volatile("barrier.cluster.wait.aligned;" ::: "memory");
}

__device__ __forceinline__ float sigmoidf_(float x) {
    return 1.0f / (1.0f + expf(-x));
}

// ---------------------------------------------------------------------------
// Transpose all 5 weight matrices (512x512): dst[k][j] = src[j][k]
// grid (16,16,5), block (32,8)
// ---------------------------------------------------------------------------
__global__ void transpose_all(const float* __restrict__ W_uz,
                              const float* __restrict__ W_ur,
                              const float* __restrict__ W_uh,
                              const float* __restrict__ W_enc,
                              const float* __restrict__ W_dec) {
    __shared__ float tile[32][33];
    const float* src;
    float* dst;
    switch (blockIdx.z) {
        case 0: src = W_uz;  dst = g_UzT; break;
        case 1: src = W_ur;  dst = g_UrT; break;
        case 2: src = W_uh;  dst = g_UhT; break;
        case 3: src = W_enc; dst = g_WeT; break;
        default: src = W_dec; dst = g_WdT; break;
    }
    const int bx = blockIdx.x * 32, by = blockIdx.y * 32;
    const int tx = threadIdx.x, ty = threadIdx.y;
#pragma unroll
    for (int i = 0; i < 32; i += 8)
        tile[ty + i][tx] = src[(size_t)(by + ty + i) * NR + bx + tx];
    __syncthreads();
#pragma unroll
    for (int i = 0; i < 32; i += 8)
        dst[(size_t)(bx + ty + i) * NR + by + tx] = tile[tx][ty + i];
}

// ---------------------------------------------------------------------------
// Encoder: g_h[b][j] = sum_k init[b][k] * WeT[k][j]
// grid (128, 4), 128 threads
// ---------------------------------------------------------------------------
__global__ void encoder_kernel(const float* __restrict__ init_state) {
    __shared__ float sI[NR];
    const int b = blockIdx.x;
    const int j = blockIdx.y * 128 + threadIdx.x;
    for (int i = threadIdx.x; i < NR; i += 128)
        sI[i] = init_state[(size_t)b * NR + i];
    __syncthreads();
    float acc = 0.0f;
#pragma unroll 8
    for (int k = 0; k < NR; k++)
        acc = fmaf(sI[k], g_WeT[(size_t)k * NR + j], acc);
    g_h[(size_t)b * NR + j] = acc;
}

// ---------------------------------------------------------------------------
// Persistent recurrent kernel.
// Grid = 128 CTAs = 16 independent clusters of 8. 512 threads/CTA.
// Cluster owns 8 batch rows; CTA owns 64 recurrent columns.
// GEMM thread tile: 4 rows x 4 cols, K split into 16 chunks of 32.
// ---------------------------------------------------------------------------
__global__ void __cluster_dims__(CL, 1, 1) __launch_bounds__(NTH, 1)
rnn_persistent(const float* __restrict__ x,
               const float* __restrict__ W_wz,
               const float* __restrict__ W_wr,
               const float* __restrict__ W_wh,
               float* __restrict__ out_h)
{
    extern __shared__ float dynsm[];
    float (*sH)[SHP]              = (float (*)[SHP])dynsm;
    float* p = dynsm + BG * SHP;
    float (*sRed)[NKC][BG][COLS]  = (float (*)[NKC][BG][COLS])p;  p += 2 * NKC * BG * COLS;
    float (*sZ)[COLS]             = (float (*)[COLS])p;           p += BG * COLS;
    float (*sHown)[COLS]          = (float (*)[COLS])p;           p += BG * COLS;
    float (*sWin)[COLS][NIN]      = (float (*)[COLS][NIN])p;      p += 3 * COLS * NIN;
    float (*sX)[NIN]              = (float (*)[NIN])p;

    const int tid     = threadIdx.x;
    const int cta     = blockIdx.x;
    const int cl      = cta / CL;
    const int rank    = cta % CL;
    const int b0      = cl * BG;
    const int colbase = rank * COLS;

    // GEMM thread mapping: warp = one K chunk; lanes span (rowgroup, colgroup).
    const int kc = tid >> 5;              // 0..15
    const int r5 = tid & 31;
    const int j0 = (r5 & 15) << 2;        // 0,4,...,60
    const int rg = (r5 >> 4) << 2;        // 0 or 4 (row base, 4 rows)
    const int kb = kc << 5;               // K chunk base (32 wide)

    // Epilogue mapping: one output element per thread (512 = 8*64).
    const int eb = tid >> 6;              // batch row 0..7
    const int ej = tid & 63;              // column 0..63

    // Load input-projection weight slices (n_in = 2).
    if (tid < COLS) {
        const int j = colbase + tid;
        sWin[0][tid][0] = W_wz[j * NIN + 0];
        sWin[0][tid][1] = W_wz[j * NIN + 1];
        sWin[1][tid][0] = W_wr[j * NIN + 0];
        sWin[1][tid][1] = W_wr[j * NIN + 1];
        sWin[2][tid][0] = W_wh[j * NIN + 0];
        sWin[2][tid][1] = W_wh[j * NIN + 1];
    }

    // Load h0 (written by encoder_kernel) into sH.
    {
        for (int i = tid; i < BG * (NR / 4); i += NTH) {
            const int b = i >> 7, idx = i & 127;
            reinterpret_cast<float4*>(&sH[b][0])[idx] =
                __ldcv(reinterpret_cast<const float4*>(g_h + (size_t)(b0 + b) * NR) + idx);
        }
    }
    __syncthreads();

    const float* __restrict__ wzBase = g_UzT + (size_t)kb * NR + colbase + j0;
    const float* __restrict__ wrBase = g_UrT + (size_t)kb * NR + colbase + j0;
    const float* __restrict__ whBase = g_UhT + (size_t)kb * NR + colbase + j0;

    for (int t = 0; t < TT; t++) {
        // Load x_t for our 8 rows.
        if (tid < BG * NIN) {
            const int b = tid >> 1, c = tid & 1;
            sX[b][c] = x[((size_t)(b0 + b) * TT + t) * NIN + c];
        }

        // ---------------- Phase 1: z, r gate GEMMs ----------------
        {
            float az[4][4] = {{0,0,0,0},{0,0,0,0},{0,0,0,0},{0,0,0,0}};
            float ar[4][4] = {{0,0,0,0},{0,0,0,0},{0,0,0,0},{0,0,0,0}};
            const float* __restrict__ h0p = &sH[rg + 0][kb];
            const float* __restrict__ h1p = &sH[rg + 1][kb];
            const float* __restrict__ h2p = &sH[rg + 2][kb];
            const float* __restrict__ h3p = &sH[rg + 3][kb];
#pragma unroll 8
            for (int k = 0; k < 32; k++) {
                const float4 wzv = *reinterpret_cast<const float4*>(wzBase + (size_t)k * NR);
                const float4 wrv = *reinterpret_cast<const float4*>(wrBase + (size_t)k * NR);
                const float hv0 = h0p[k], hv1 = h1p[k], hv2 = h2p[k], hv3 = h3p[k];
                az[0][0] = fmaf(hv0, wzv.x, az[0][0]); az[0][1] = fmaf(hv0, wzv.y, az[0][1]);
                az[0][2] = fmaf(hv0, wzv.z, az[0][2]); az[0][3] = fmaf(hv0, wzv.w, az[0][3]);
                az[1][0] = fmaf(hv1, wzv.x, az[1][0]); az[1][1] = fmaf(hv1, wzv.y, az[1][1]);
                az[1][2] = fmaf(hv1, wzv.z, az[1][2]); az[1][3] = fmaf(hv1, wzv.w, az[1][3]);
                az[2][0] = fmaf(hv2, wzv.x, az[2][0]); az[2][1] = fmaf(hv2, wzv.y, az[2][1]);
                az[2][2] = fmaf(hv2, wzv.z, az[2][2]); az[2][3] = fmaf(hv2, wzv.w, az[2][3]);
                az[3][0] = fmaf(hv3, wzv.x, az[3][0]); az[3][1] = fmaf(hv3, wzv.y, az[3][1]);
                az[3][2] = fmaf(hv3, wzv.z, az[3][2]); az[3][3] = fmaf(hv3, wzv.w, az[3][3]);
                ar[0][0] = fmaf(hv0, wrv.x, ar[0][0]); ar[0][1] = fmaf(hv0, wrv.y, ar[0][1]);
                ar[0][2] = fmaf(hv0, wrv.z, ar[0][2]); ar[0][3] = fmaf(hv0, wrv.w, ar[0][3]);
                ar[1][0] = fmaf(hv1, wrv.x, ar[1][0]); ar[1][1] = fmaf(hv1, wrv.y, ar[1][1]);
                ar[1][2] = fmaf(hv1, wrv.z, ar[1][2]); ar[1][3] = fmaf(hv1, wrv.w, ar[1][3]);
                ar[2][0] = fmaf(hv2, wrv.x, ar[2][0]); ar[2][1] = fmaf(hv2, wrv.y, ar[2][1]);
                ar[2][2] = fmaf(hv2, wrv.z, ar[2][2]); ar[2][3] = fmaf(hv2, wrv.w, ar[2][3]);
                ar[3][0] = fmaf(hv3, wrv.x, ar[3][0]); ar[3][1] = fmaf(hv3, wrv.y, ar[3][1]);
                ar[3][2] = fmaf(hv3, wrv.z, ar[3][2]); ar[3][3] = fmaf(hv3, wrv.w, ar[3][3]);
            }
#pragma unroll
            for (int b = 0; b < 4; b++) {
                *reinterpret_cast<float4*>(&sRed[0][kc][rg + b][j0]) =
                    make_float4(az[b][0], az[b][1], az[b][2], az[b][3]);
                *reinterpret_cast<float4*>(&sRed[1][kc][rg + b][j0]) =
                    make_float4(ar[b][0], ar[b][1], ar[b][2], ar[b][3]);
            }
        }
        __syncthreads();

        // Phase 1 epilogue: reduce chunks, gates, v = r*h (own slice -> g_v).
        {
            float sz = 0.0f, sr = 0.0f;
#pragma unroll
            for (int c = 0; c < NKC; c++) {
                sz += sRed[0][c][eb][ej];
                sr += sRed[1][c][eb][ej];
            }
            const float xz = sX[eb][0] * sWin[0][ej][0] + sX[eb][1] * sWin[0][ej][1];
            const float xr = sX[eb][0] * sWin[1][ej][0] + sX[eb][1] * sWin[1][ej][1];
            const float z  = sigmoidf_(xz + sz);
            const float r  = sigmoidf_(xr + sr);
            const float hc = sH[eb][colbase + ej];
            sZ[eb][ej]    = z;
            sHown[eb][ej] = hc;
            g_v[(size_t)(b0 + eb) * NR + colbase + ej] = r * hc;
        }
        cluster_sync_all();   // all v slices visible cluster-wide

        // Refill sH with full v.
        for (int i = tid; i < BG * (NR / 4); i += NTH) {
            const int b = i >> 7, idx = i & 127;
            reinterpret_cast<float4*>(&sH[b][0])[idx] =
                __ldcv(reinterpret_cast<const float4*>(g_v + (size_t)(b0 + b) * NR) + idx);
        }
        __syncthreads();

        // ---------------- Phase 2: candidate GEMM (v @ Uh^T) ----------------
        {
            float au[4][4] = {{0,0,0,0},{0,0,0,0},{0,0,0,0},{0,0,0,0}};
            const float* __restrict__ v0p = &sH[rg + 0][kb];
            const float* __restrict__ v1p = &sH[rg + 1][kb];
            const float* __restrict__ v2p = &sH[rg + 2][kb];
            const float* __restrict__ v3p = &sH[rg + 3][kb];
#pragma unroll 8
            for (int k = 0; k < 32; k++) {
                const float4 wv = *reinterpret_cast<const float4*>(whBase + (size_t)k * NR);
                const float v0 = v0p[k], v1 = v1p[k], v2 = v2p[k], v3 = v3p[k];
                au[0][0] = fmaf(v0, wv.x, au[0][0]); au[0][1] = fmaf(v0, wv.y, au[0][1]);
                au[0][2] = fmaf(v0, wv.z, au[0][2]); au[0][3] = fmaf(v0, wv.w, au[0][3]);
                au[1][0] = fmaf(v1, wv.x, au[1][0]); au[1][1] = fmaf(v1, wv.y, au[1][1]);
                au[1][2] = fmaf(v1, wv.z, au[1][2]); au[1][3] = fmaf(v1, wv.w, au[1][3]);
                au[2][0] = fmaf(v2, wv.x, au[2][0]); au[2][1] = fmaf(v2, wv.y, au[2][1]);
                au[2][2] = fmaf(v2, wv.z, au[2][2]); au[2][3] = fmaf(v2, wv.w, au[2][3]);
                au[3][0] = fmaf(v3, wv.x, au[3][0]); au[3][1] = fmaf(v3, wv.y, au[3][1]);
                au[3][2] = fmaf(v3, wv.z, au[3][2]); au[3][3] = fmaf(v3, wv.w, au[3][3]);
            }
#pragma unroll
            for (int b = 0; b < 4; b++)
                *reinterpret_cast<float4*>(&sRed[0][kc][rg + b][j0]) =
                    make_float4(au[b][0], au[b][1], au[b][2], au[b][3]);
        }
        __syncthreads();

        // Phase 2 epilogue: u, tanh, leaky update; write h_t to output + g_h.
        {
            float su = 0.0f;
#pragma unroll
            for (int c = 0; c < NKC; c++)
                su += sRed[0][c][eb][ej];
            const float xh = sX[eb][0] * sWin[2][ej][0] + sX[eb][1] * sWin[2][ej][1];
            const float u  = xh + su;
            const float hc = sHown[eb][ej];
            const float z  = sZ[eb][ej];
            const float hn = hc + DTAU * (z - 1.0f) * (hc - tanhf(u));
            out_h[((size_t)(b0 + eb) * TT + t) * NR + colbase + ej] = hn;
            g_h[(size_t)(b0 + eb) * NR + colbase + ej] = hn;
        }
        cluster_sync_all();   // all new-h slices visible cluster-wide

        // Refill sH with full new h for next step.
        for (int i = tid; i < BG * (NR / 4); i += NTH) {
            const int b = i >> 7, idx = i & 127;
            reinterpret_cast<float4*>(&sH[b][0])[idx] =
                __ldcv(reinterpret_cast<const float4*>(g_h + (size_t)(b0 + b) * NR) + idx);
        }
        __syncthreads();
    }
}

// ---------------------------------------------------------------------------
// Decoder GEMM: y[bt][o] = sum_r h[bt][r] * W_dec[o][r]
//             = A (65536 x 512) * g_WdT (512 x 512)
// 128x128 block tile, K-tile 8, 8x8 thread tile (2x2 quadrants of 4).
// grid (4, 512), 256 threads.
// ---------------------------------------------------------------------------
__global__ void __launch_bounds__(256)
decoder_gemm(const float* __restrict__ A, float* __restrict__ C) {
    __shared__ float As[8][128];
    __shared__ float Bs[8][128];

    const int tid = threadIdx.x;
    const int tx = tid & 15;       // 16
    const int ty = tid >> 4;       // 16
    const int m0 = blockIdx.y * 128;
    const int n0 = blockIdx.x * 128;

    float acc[8][8];
#pragma unroll
    for (int i = 0; i < 8; i++)
#pragma unroll
        for (int j = 0; j < 8; j++) acc[i][j] = 0.0f;

    const int lrow = tid >> 1;          // 0..127
    const int lk   = (tid & 1) << 2;    // 0 or 4
    const int brow = tid >> 5;          // 0..7
    const int bcol = (tid & 31) << 2;   // 0..124

    for (int k0 = 0; k0 < NR; k0 += 8) {
        const float4 av = *reinterpret_cast<const float4*>(
            A + (size_t)(m0 + lrow) * NR + k0 + lk);
        As[lk + 0][lrow] = av.x;
        As[lk + 1][lrow] = av.y;
        As[lk + 2][lrow] = av.z;
        As[lk + 3][lrow] = av.w;
        *reinterpret_cast<float4*>(&Bs[brow][bcol]) =
            *reinterpret_cast<const float4*>(
                g_WdT + (size_t)(k0 + brow) * NR + n0 + bcol);
        __syncthreads();

#pragma unroll
        for (int kk = 0; kk < 8; kk++) {
            float a[8], b[8];
            *reinterpret_cast<float4*>(a)     = *reinterpret_cast<const float4*>(&As[kk][ty * 4]);
            *reinterpret_cast<float4*>(a + 4) = *reinterpret_cast<const float4*>(&As[kk][64 + ty * 4]);
            *reinterpret_cast<float4*>(b)     = *reinterpret_cast<const float4*>(&Bs[kk][tx * 4]);
            *reinterpret_cast<float4*>(b + 4) = *reinterpret_cast<const float4*>(&Bs[kk][64 + tx * 4]);
#pragma unroll
            for (int i = 0; i < 8; i++)
#pragma unroll
                for (int j = 0; j < 8; j++)
                    acc[i][j] = fmaf(a[i], b[j], acc[i][j]);
        }
        __syncthreads();
    }

#pragma unroll
    for (int ri = 0; ri < 2; ri++) {
#pragma unroll
        for (int i = 0; i < 4; i++) {
            const int row = m0 + ri * 64 + ty * 4 + i;
            const int ii = ri * 4 + i;
            *reinterpret_cast<float4*>(C + (size_t)row * NR + n0 + tx * 4) =
                make_float4(acc[ii][0], acc[ii][1], acc[ii][2], acc[ii][3]);
            *reinterpret_cast<float4*>(C + (size_t)row * NR + n0 + 64 + tx * 4) =
                make_float4(acc[ii][4], acc[ii][5], acc[ii][6], acc[ii][7]);
        }
    }
}

// ---------------------------------------------------------------------------
// Launch. Inputs (metadata order): x, init_state, W_enc, W_wz, W_uz, W_wr,
// W_ur, W_wh, W_uh, W_dec. Output: [h_1t | y_1t] concatenated,
// each (B, T, NR) fp32.
// ---------------------------------------------------------------------------
extern "C" void kernel_launch(void* const* d_in, const int* in_sizes, int n_in,
                              void* d_out, int out_size) {
    const float* x     = (const float*)d_in[0];
    const float* init  = (const float*)d_in[1];
    const float* W_enc = (const float*)d_in[2];
    const float* W_wz  = (const float*)d_in[3];
    const float* W_uz  = (const float*)d_in[4];
    const float* W_wr  = (const float*)d_in[5];
    const float* W_ur  = (const float*)d_in[6];
    const float* W_wh  = (const float*)d_in[7];
    const float* W_uh  = (const float*)d_in[8];
    const float* W_dec = (const float*)d_in[9];

    float* out_h = (float*)d_out;
    float* out_y = out_h + (size_t)BN * TT * NR;

    cudaFuncSetAttribute(rnn_persistent,
                         cudaFuncAttributeMaxDynamicSharedMemorySize, SM_BYTES);

    transpose_all<<<dim3(16, 16, 5), dim3(32, 8)>>>(W_uz, W_ur, W_uh, W_enc, W_dec);
    encoder_kernel<<<dim3(BN, 4), 128>>>(init);
    rnn_persistent<<<BN, NTH, SM_BYTES>>>(x, W_wz, W_wr, W_wh, out_h);
    decoder_gemm<<<dim3(4, 512), 256>>>(out_h, out_y);
}

// round 13
// speedup vs baseline: 1.1165x; 1.0604x over previous
#include <cuda_runtime.h>
#include <math.h>

// ---------------------------------------------------------------------------
// Problem constants (fixed by setup_inputs):
//   B=128, T=512, n_in=2, n_rec = n_out = n_init = 512
// ---------------------------------------------------------------------------
#define BN   128
#define TT   512
#define NR   512
#define NIN  2
#define CL   8      // CTAs per cluster
#define BG   8      // batch rows per cluster (128 rows / 16 clusters)
#define COLS 64     // n_rec columns per CTA (512 / 8)
#define NTH  512    // threads per CTA (16 warps)
#define NKC  16     // K chunks (32 k each)
#define SHP  (NR + 4)   // padded sH row pitch (kills LDS bank conflicts)
#define DTAU 0.2f

// Dynamic smem layout (floats):
//   sUh   [NR][COLS]           32768   (persistent Uh weight slice)
//   sH    [BG][SHP]             4128
//   sRed  [2][NKC][BG][COLS]   16384
//   sZ    [BG][COLS]             512
//   sHown [BG][COLS]             512
//   sWin  [3][COLS][NIN]         384
//   sX    [BG][NIN]               16
#define SM_FLOATS (NR*COLS + BG*SHP + 2*NKC*BG*COLS + BG*COLS + BG*COLS + 3*COLS*NIN + BG*NIN)
#define SM_BYTES  (SM_FLOATS * 4)

// Static device scratch (no allocation allowed).
__device__ float g_h[BN * NR];     // h exchange buffer (full state)
__device__ float g_v[BN * NR];     // v = r*h exchange buffer
__device__ float g_UzT[NR * NR];   // W_uz transposed: [k][j]
__device__ float g_UrT[NR * NR];
__device__ float g_UhT[NR * NR];
__device__ float g_WeT[NR * NR];   // W_enc transposed
__device__ float g_WdT[NR * NR];   // W_dec transposed

__device__ __forceinline__ void cluster_sync_all() {
    asm volatile("barrier.cluster.arrive.aligned;" ::: "memory");
    asm volatile("barrier.cluster.wait.aligned;" ::: "memory");
}

__device__ __forceinline__ float sigmoidf_(float x) {
    return 1.0f / (1.0f + expf(-x));
}

// ---------------------------------------------------------------------------
// Transpose all 5 weight matrices (512x512): dst[k][j] = src[j][k]
// grid (16,16,5), block (32,8)
// ---------------------------------------------------------------------------
__global__ void transpose_all(const float* __restrict__ W_uz,
                              const float* __restrict__ W_ur,
                              const float* __restrict__ W_uh,
                              const float* __restrict__ W_enc,
                              const float* __restrict__ W_dec) {
    __shared__ float tile[32][33];
    const float* src;
    float* dst;
    switch (blockIdx.z) {
        case 0: src = W_uz;  dst = g_UzT; break;
        case 1: src = W_ur;  dst = g_UrT; break;
        case 2: src = W_uh;  dst = g_UhT; break;
        case 3: src = W_enc; dst = g_WeT; break;
        default: src = W_dec; dst = g_WdT; break;
    }
    const int bx = blockIdx.x * 32, by = blockIdx.y * 32;
    const int tx = threadIdx.x, ty = threadIdx.y;
#pragma unroll
    for (int i = 0; i < 32; i += 8)
        tile[ty + i][tx] = src[(size_t)(by + ty + i) * NR + bx + tx];
    __syncthreads();
#pragma unroll
    for (int i = 0; i < 32; i += 8)
        dst[(size_t)(bx + ty + i) * NR + by + tx] = tile[tx][ty + i];
}

// ---------------------------------------------------------------------------
// Encoder: g_h[b][j] = sum_k init[b][k] * WeT[k][j]
// grid (128, 4), 128 threads
// ---------------------------------------------------------------------------
__global__ void encoder_kernel(const float* __restrict__ init_state) {
    __shared__ float sI[NR];
    const int b = blockIdx.x;
    const int j = blockIdx.y * 128 + threadIdx.x;
    for (int i = threadIdx.x; i < NR; i += 128)
        sI[i] = init_state[(size_t)b * NR + i];
    __syncthreads();
    float acc = 0.0f;
#pragma unroll 8
    for (int k = 0; k < NR; k++)
        acc = fmaf(sI[k], g_WeT[(size_t)k * NR + j], acc);
    g_h[(size_t)b * NR + j] = acc;
}

// ---------------------------------------------------------------------------
// Persistent recurrent kernel.
// Grid = 128 CTAs = 16 independent clusters of 8. 512 threads/CTA.
// Cluster owns 8 batch rows; CTA owns 64 recurrent columns.
// GEMM thread tile: 4 rows x 4 cols, K split into 16 chunks of 32.
// Phase-2 weights (Uh slice, 128KB) live permanently in SMEM.
// ---------------------------------------------------------------------------
__global__ void __cluster_dims__(CL, 1, 1) __launch_bounds__(NTH, 1)
rnn_persistent(const float* __restrict__ x,
               const float* __restrict__ W_wz,
               const float* __restrict__ W_wr,
               const float* __restrict__ W_wh,
               float* __restrict__ out_h)
{
    extern __shared__ float dynsm[];
    float (*sUh)[COLS]            = (float (*)[COLS])dynsm;
    float* p = dynsm + NR * COLS;
    float (*sH)[SHP]              = (float (*)[SHP])p;            p += BG * SHP;
    float (*sRed)[NKC][BG][COLS]  = (float (*)[NKC][BG][COLS])p;  p += 2 * NKC * BG * COLS;
    float (*sZ)[COLS]             = (float (*)[COLS])p;           p += BG * COLS;
    float (*sHown)[COLS]          = (float (*)[COLS])p;           p += BG * COLS;
    float (*sWin)[COLS][NIN]      = (float (*)[COLS][NIN])p;      p += 3 * COLS * NIN;
    float (*sX)[NIN]              = (float (*)[NIN])p;

    const int tid     = threadIdx.x;
    const int cta     = blockIdx.x;
    const int cl      = cta / CL;
    const int rank    = cta % CL;
    const int b0      = cl * BG;
    const int colbase = rank * COLS;

    // GEMM thread mapping: warp = one K chunk; lanes span (rowgroup, colgroup).
    const int kc = tid >> 5;              // 0..15
    const int r5 = tid & 31;
    const int j0 = (r5 & 15) << 2;        // 0,4,...,60
    const int rg = (r5 >> 4) << 2;        // 0 or 4 (row base, 4 rows)
    const int kb = kc << 5;               // K chunk base (32 wide)

    // Epilogue mapping: one output element per thread (512 = 8*64).
    const int eb = tid >> 6;              // batch row 0..7
    const int ej = tid & 63;              // column 0..63

    // Load input-projection weight slices (n_in = 2).
    if (tid < COLS) {
        const int j = colbase + tid;
        sWin[0][tid][0] = W_wz[j * NIN + 0];
        sWin[0][tid][1] = W_wz[j * NIN + 1];
        sWin[1][tid][0] = W_wr[j * NIN + 0];
        sWin[1][tid][1] = W_wr[j * NIN + 1];
        sWin[2][tid][0] = W_wh[j * NIN + 0];
        sWin[2][tid][1] = W_wh[j * NIN + 1];
    }

    // Preload the Uh column slice into SMEM (persistent for all 512 steps).
    // sUh[k][j] = g_UhT[k][colbase + j]; 8192 float4 total, 16 per thread.
    for (int i = tid; i < NR * (COLS / 4); i += NTH) {
        const int k = i >> 4, jf = i & 15;
        reinterpret_cast<float4*>(&sUh[k][0])[jf] =
            __ldcg(reinterpret_cast<const float4*>(g_UhT + (size_t)k * NR + colbase) + jf);
    }

    // Load h0 (written by encoder_kernel) into sH.
    for (int i = tid; i < BG * (NR / 4); i += NTH) {
        const int b = i >> 7, idx = i & 127;
        reinterpret_cast<float4*>(&sH[b][0])[idx] =
            __ldcv(reinterpret_cast<const float4*>(g_h + (size_t)(b0 + b) * NR) + idx);
    }
    __syncthreads();

    const float* __restrict__ wzBase = g_UzT + (size_t)kb * NR + colbase + j0;
    const float* __restrict__ wrBase = g_UrT + (size_t)kb * NR + colbase + j0;

    for (int t = 0; t < TT; t++) {
        // Load x_t for our 8 rows.
        if (tid < BG * NIN) {
            const int b = tid >> 1, c = tid & 1;
            sX[b][c] = x[((size_t)(b0 + b) * TT + t) * NIN + c];
        }

        // ---------------- Phase 1: z, r gate GEMMs (weights from L2) --------
        {
            float az[4][4] = {{0,0,0,0},{0,0,0,0},{0,0,0,0},{0,0,0,0}};
            float ar[4][4] = {{0,0,0,0},{0,0,0,0},{0,0,0,0},{0,0,0,0}};
            const float* __restrict__ h0p = &sH[rg + 0][kb];
            const float* __restrict__ h1p = &sH[rg + 1][kb];
            const float* __restrict__ h2p = &sH[rg + 2][kb];
            const float* __restrict__ h3p = &sH[rg + 3][kb];
#pragma unroll 8
            for (int k = 0; k < 32; k++) {
                const float4 wzv = __ldcg(reinterpret_cast<const float4*>(wzBase + (size_t)k * NR));
                const float4 wrv = __ldcg(reinterpret_cast<const float4*>(wrBase + (size_t)k * NR));
                const float hv0 = h0p[k], hv1 = h1p[k], hv2 = h2p[k], hv3 = h3p[k];
                az[0][0] = fmaf(hv0, wzv.x, az[0][0]); az[0][1] = fmaf(hv0, wzv.y, az[0][1]);
                az[0][2] = fmaf(hv0, wzv.z, az[0][2]); az[0][3] = fmaf(hv0, wzv.w, az[0][3]);
                az[1][0] = fmaf(hv1, wzv.x, az[1][0]); az[1][1] = fmaf(hv1, wzv.y, az[1][1]);
                az[1][2] = fmaf(hv1, wzv.z, az[1][2]); az[1][3] = fmaf(hv1, wzv.w, az[1][3]);
                az[2][0] = fmaf(hv2, wzv.x, az[2][0]); az[2][1] = fmaf(hv2, wzv.y, az[2][1]);
                az[2][2] = fmaf(hv2, wzv.z, az[2][2]); az[2][3] = fmaf(hv2, wzv.w, az[2][3]);
                az[3][0] = fmaf(hv3, wzv.x, az[3][0]); az[3][1] = fmaf(hv3, wzv.y, az[3][1]);
                az[3][2] = fmaf(hv3, wzv.z, az[3][2]); az[3][3] = fmaf(hv3, wzv.w, az[3][3]);
                ar[0][0] = fmaf(hv0, wrv.x, ar[0][0]); ar[0][1] = fmaf(hv0, wrv.y, ar[0][1]);
                ar[0][2] = fmaf(hv0, wrv.z, ar[0][2]); ar[0][3] = fmaf(hv0, wrv.w, ar[0][3]);
                ar[1][0] = fmaf(hv1, wrv.x, ar[1][0]); ar[1][1] = fmaf(hv1, wrv.y, ar[1][1]);
                ar[1][2] = fmaf(hv1, wrv.z, ar[1][2]); ar[1][3] = fmaf(hv1, wrv.w, ar[1][3]);
                ar[2][0] = fmaf(hv2, wrv.x, ar[2][0]); ar[2][1] = fmaf(hv2, wrv.y, ar[2][1]);
                ar[2][2] = fmaf(hv2, wrv.z, ar[2][2]); ar[2][3] = fmaf(hv2, wrv.w, ar[2][3]);
                ar[3][0] = fmaf(hv3, wrv.x, ar[3][0]); ar[3][1] = fmaf(hv3, wrv.y, ar[3][1]);
                ar[3][2] = fmaf(hv3, wrv.z, ar[3][2]); ar[3][3] = fmaf(hv3, wrv.w, ar[3][3]);
            }
#pragma unroll
            for (int b = 0; b < 4; b++) {
                *reinterpret_cast<float4*>(&sRed[0][kc][rg + b][j0]) =
                    make_float4(az[b][0], az[b][1], az[b][2], az[b][3]);
                *reinterpret_cast<float4*>(&sRed[1][kc][rg + b][j0]) =
                    make_float4(ar[b][0], ar[b][1], ar[b][2], ar[b][3]);
            }
        }
        __syncthreads();

        // Phase 1 epilogue: reduce chunks, gates, v = r*h (own slice -> g_v).
        {
            float sz = 0.0f, sr = 0.0f;
#pragma unroll
            for (int c = 0; c < NKC; c++) {
                sz += sRed[0][c][eb][ej];
                sr += sRed[1][c][eb][ej];
            }
            const float xz = sX[eb][0] * sWin[0][ej][0] + sX[eb][1] * sWin[0][ej][1];
            const float xr = sX[eb][0] * sWin[1][ej][0] + sX[eb][1] * sWin[1][ej][1];
            const float z  = sigmoidf_(xz + sz);
            const float r  = sigmoidf_(xr + sr);
            const float hc = sH[eb][colbase + ej];
            sZ[eb][ej]    = z;
            sHown[eb][ej] = hc;
            g_v[(size_t)(b0 + eb) * NR + colbase + ej] = r * hc;
        }
        cluster_sync_all();   // all v slices visible cluster-wide

        // Refill sH with full v.
        for (int i = tid; i < BG * (NR / 4); i += NTH) {
            const int b = i >> 7, idx = i & 127;
            reinterpret_cast<float4*>(&sH[b][0])[idx] =
                __ldcv(reinterpret_cast<const float4*>(g_v + (size_t)(b0 + b) * NR) + idx);
        }
        __syncthreads();

        // ---------------- Phase 2: candidate GEMM (weights from SMEM) -------
        {
            float au[4][4] = {{0,0,0,0},{0,0,0,0},{0,0,0,0},{0,0,0,0}};
            const float* __restrict__ v0p = &sH[rg + 0][kb];
            const float* __restrict__ v1p = &sH[rg + 1][kb];
            const float* __restrict__ v2p = &sH[rg + 2][kb];
            const float* __restrict__ v3p = &sH[rg + 3][kb];
#pragma unroll 8
            for (int k = 0; k < 32; k++) {
                const float4 wv = *reinterpret_cast<const float4*>(&sUh[kb + k][j0]);
                const float v0 = v0p[k], v1 = v1p[k], v2 = v2p[k], v3 = v3p[k];
                au[0][0] = fmaf(v0, wv.x, au[0][0]); au[0][1] = fmaf(v0, wv.y, au[0][1]);
                au[0][2] = fmaf(v0, wv.z, au[0][2]); au[0][3] = fmaf(v0, wv.w, au[0][3]);
                au[1][0] = fmaf(v1, wv.x, au[1][0]); au[1][1] = fmaf(v1, wv.y, au[1][1]);
                au[1][2] = fmaf(v1, wv.z, au[1][2]); au[1][3] = fmaf(v1, wv.w, au[1][3]);
                au[2][0] = fmaf(v2, wv.x, au[2][0]); au[2][1] = fmaf(v2, wv.y, au[2][1]);
                au[2][2] = fmaf(v2, wv.z, au[2][2]); au[2][3] = fmaf(v2, wv.w, au[2][3]);
                au[3][0] = fmaf(v3, wv.x, au[3][0]); au[3][1] = fmaf(v3, wv.y, au[3][1]);
                au[3][2] = fmaf(v3, wv.z, au[3][2]); au[3][3] = fmaf(v3, wv.w, au[3][3]);
            }
#pragma unroll
            for (int b = 0; b < 4; b++)
                *reinterpret_cast<float4*>(&sRed[0][kc][rg + b][j0]) =
                    make_float4(au[b][0], au[b][1], au[b][2], au[b][3]);
        }
        __syncthreads();

        // Phase 2 epilogue: u, tanh, leaky update; write h_t to output + g_h.
        {
            float su = 0.0f;
#pragma unroll
            for (int c = 0; c < NKC; c++)
                su += sRed[0][c][eb][ej];
            const float xh = sX[eb][0] * sWin[2][ej][0] + sX[eb][1] * sWin[2][ej][1];
            const float u  = xh + su;
            const float hc = sHown[eb][ej];
            const float z  = sZ[eb][ej];
            const float hn = hc + DTAU * (z - 1.0f) * (hc - tanhf(u));
            out_h[((size_t)(b0 + eb) * TT + t) * NR + colbase + ej] = hn;
            g_h[(size_t)(b0 + eb) * NR + colbase + ej] = hn;
        }
        cluster_sync_all();   // all new-h slices visible cluster-wide

        // Refill sH with full new h for next step.
        for (int i = tid; i < BG * (NR / 4); i += NTH) {
            const int b = i >> 7, idx = i & 127;
            reinterpret_cast<float4*>(&sH[b][0])[idx] =
                __ldcv(reinterpret_cast<const float4*>(g_h + (size_t)(b0 + b) * NR) + idx);
        }
        __syncthreads();
    }
}

// ---------------------------------------------------------------------------
// Decoder GEMM: y[bt][o] = sum_r h[bt][r] * W_dec[o][r]
//             = A (65536 x 512) * g_WdT (512 x 512)
// 128x128 block tile, K-tile 8, 8x8 thread tile (2x2 quadrants of 4).
// grid (4, 512), 256 threads.
// ---------------------------------------------------------------------------
__global__ void __launch_bounds__(256)
decoder_gemm(const float* __restrict__ A, float* __restrict__ C) {
    __shared__ float As[8][128];
    __shared__ float Bs[8][128];

    const int tid = threadIdx.x;
    const int tx = tid & 15;       // 16
    const int ty = tid >> 4;       // 16
    const int m0 = blockIdx.y * 128;
    const int n0 = blockIdx.x * 128;

    float acc[8][8];
#pragma unroll
    for (int i = 0; i < 8; i++)
#pragma unroll
        for (int j = 0; j < 8; j++) acc[i][j] = 0.0f;

    const int lrow = tid >> 1;          // 0..127
    const int lk   = (tid & 1) << 2;    // 0 or 4
    const int brow = tid >> 5;          // 0..7
    const int bcol = (tid & 31) << 2;   // 0..124

    for (int k0 = 0; k0 < NR; k0 += 8) {
        const float4 av = *reinterpret_cast<const float4*>(
            A + (size_t)(m0 + lrow) * NR + k0 + lk);
        As[lk + 0][lrow] = av.x;
        As[lk + 1][lrow] = av.y;
        As[lk + 2][lrow] = av.z;
        As[lk + 3][lrow] = av.w;
        *reinterpret_cast<float4*>(&Bs[brow][bcol]) =
            *reinterpret_cast<const float4*>(
                g_WdT + (size_t)(k0 + brow) * NR + n0 + bcol);
        __syncthreads();

#pragma unroll
        for (int kk = 0; kk < 8; kk++) {
            float a[8], b[8];
            *reinterpret_cast<float4*>(a)     = *reinterpret_cast<const float4*>(&As[kk][ty * 4]);
            *reinterpret_cast<float4*>(a + 4) = *reinterpret_cast<const float4*>(&As[kk][64 + ty * 4]);
            *reinterpret_cast<float4*>(b)     = *reinterpret_cast<const float4*>(&Bs[kk][tx * 4]);
            *reinterpret_cast<float4*>(b + 4) = *reinterpret_cast<const float4*>(&Bs[kk][64 + tx * 4]);
#pragma unroll
            for (int i = 0; i < 8; i++)
#pragma unroll
                for (int j = 0; j < 8; j++)
                    acc[i][j] = fmaf(a[i], b[j], acc[i][j]);
        }
        __syncthreads();
    }

#pragma unroll
    for (int ri = 0; ri < 2; ri++) {
#pragma unroll
        for (int i = 0; i < 4; i++) {
            const int row = m0 + ri * 64 + ty * 4 + i;
            const int ii = ri * 4 + i;
            *reinterpret_cast<float4*>(C + (size_t)row * NR + n0 + tx * 4) =
                make_float4(acc[ii][0], acc[ii][1], acc[ii][2], acc[ii][3]);
            *reinterpret_cast<float4*>(C + (size_t)row * NR + n0 + 64 + tx * 4) =
                make_float4(acc[ii][4], acc[ii][5], acc[ii][6], acc[ii][7]);
        }
    }
}

// ---------------------------------------------------------------------------
// Launch. Inputs (metadata order): x, init_state, W_enc, W_wz, W_uz, W_wr,
// W_ur, W_wh, W_uh, W_dec. Output: [h_1t | y_1t] concatenated,
// each (B, T, NR) fp32.
// ---------------------------------------------------------------------------
extern "C" void kernel_launch(void* const* d_in, const int* in_sizes, int n_in,
                              void* d_out, int out_size) {
    const float* x     = (const float*)d_in[0];
    const float* init  = (const float*)d_in[1];
    const float* W_enc = (const float*)d_in[2];
    const float* W_wz  = (const float*)d_in[3];
    const float* W_uz  = (const float*)d_in[4];
    const float* W_wr  = (const float*)d_in[5];
    const float* W_ur  = (const float*)d_in[6];
    const float* W_wh  = (const float*)d_in[7];
    const float* W_uh  = (const float*)d_in[8];
    const float* W_dec = (const float*)d_in[9];

    float* out_h = (float*)d_out;
    float* out_y = out_h + (size_t)BN * TT * NR;

    cudaFuncSetAttribute(rnn_persistent,
                         cudaFuncAttributeMaxDynamicSharedMemorySize, SM_BYTES);

    transpose_all<<<dim3(16, 16, 5), dim3(32, 8)>>>(W_uz, W_ur, W_uh, W_enc, W_dec);
    encoder_kernel<<<dim3(BN, 4), 128>>>(init);
    rnn_persistent<<<BN, NTH, SM_BYTES>>>(x, W_wz, W_wr, W_wh, out_h);
    decoder_gemm<<<dim3(4, 512), 256>>>(out_h, out_y);
}

// round 16
// speedup vs baseline: 1.1171x; 1.0005x over previous
#include <cuda_runtime.h>
#include <math.h>

// ---------------------------------------------------------------------------
// Problem constants (fixed by setup_inputs):
//   B=128, T=512, n_in=2, n_rec = n_out = n_init = 512
// ---------------------------------------------------------------------------
#define BN   128
#define TT   512
#define NR   512
#define NIN  2
#define CL   8      // CTAs per cluster
#define BG   8      // batch rows per cluster (128 rows / 16 clusters)
#define COLS 64     // n_rec columns per CTA (512 / 8)
#define NTH  512    // threads per CTA (16 warps)
#define NKC  16     // K chunks (32 k each)
#define SHP  (NR + 4)   // padded sH row pitch (kills LDS bank conflicts)
#define DTAU 0.2f

// Dynamic smem layout (floats):
//   sUh   [NR][COLS]           32768   (persistent Uh weight slice)
//   sH    [BG][SHP]             4128
//   sRed  [2][NKC][BG][COLS]   16384
//   sZ    [BG][COLS]             512
//   sHown [BG][COLS]             512
//   sWin  [3][COLS][NIN]         384
//   sX    [BG][NIN]               16
#define SM_FLOATS (NR*COLS + BG*SHP + 2*NKC*BG*COLS + BG*COLS + BG*COLS + 3*COLS*NIN + BG*NIN)
#define SM_BYTES  (SM_FLOATS * 4)

// Static device scratch (no allocation allowed).
__device__ float g_h[BN * NR];     // h exchange buffer (full state)
__device__ float g_v[BN * NR];     // v = r*h exchange buffer
__device__ float g_UzT[NR * NR];   // W_uz transposed: [k][j]
__device__ float g_UrT[NR * NR];
__device__ float g_UhT[NR * NR];
__device__ float g_WeT[NR * NR];   // W_enc transposed
__device__ float g_WdT[NR * NR];   // W_dec transposed

__device__ __forceinline__ void cluster_sync_all() {
    asm volatile("barrier.cluster.arrive.aligned;" ::: "memory");
    asm volatile("barrier.cluster.wait.aligned;" ::: "memory");
}

__device__ __forceinline__ float sigmoidf_(float x) {
    return 1.0f / (1.0f + expf(-x));
}

// ---------------------------------------------------------------------------
// Transpose all 5 weight matrices (512x512): dst[k][j] = src[j][k]
// grid (16,16,5), block (32,8)
// ---------------------------------------------------------------------------
__global__ void transpose_all(const float* __restrict__ W_uz,
                              const float* __restrict__ W_ur,
                              const float* __restrict__ W_uh,
                              const float* __restrict__ W_enc,
                              const float* __restrict__ W_dec) {
    __shared__ float tile[32][33];
    const float* src;
    float* dst;
    switch (blockIdx.z) {
        case 0: src = W_uz;  dst = g_UzT; break;
        case 1: src = W_ur;  dst = g_UrT; break;
        case 2: src = W_uh;  dst = g_UhT; break;
        case 3: src = W_enc; dst = g_WeT; break;
        default: src = W_dec; dst = g_WdT; break;
    }
    const int bx = blockIdx.x * 32, by = blockIdx.y * 32;
    const int tx = threadIdx.x, ty = threadIdx.y;
#pragma unroll
    for (int i = 0; i < 32; i += 8)
        tile[ty + i][tx] = src[(size_t)(by + ty + i) * NR + bx + tx];
    __syncthreads();
#pragma unroll
    for (int i = 0; i < 32; i += 8)
        dst[(size_t)(bx + ty + i) * NR + by + tx] = tile[tx][ty + i];
}

// ---------------------------------------------------------------------------
// Encoder: g_h[b][j] = sum_k init[b][k] * WeT[k][j]
// grid (128, 4), 128 threads
// ---------------------------------------------------------------------------
__global__ void encoder_kernel(const float* __restrict__ init_state) {
    __shared__ float sI[NR];
    const int b = blockIdx.x;
    const int j = blockIdx.y * 128 + threadIdx.x;
    for (int i = threadIdx.x; i < NR; i += 128)
        sI[i] = init_state[(size_t)b * NR + i];
    __syncthreads();
    float acc = 0.0f;
#pragma unroll 8
    for (int k = 0; k < NR; k++)
        acc = fmaf(sI[k], g_WeT[(size_t)k * NR + j], acc);
    g_h[(size_t)b * NR + j] = acc;
}

// ---------------------------------------------------------------------------
// Persistent recurrent kernel.
// Grid = 128 CTAs = 16 independent clusters of 8. 512 threads/CTA.
// Cluster owns 8 batch rows; CTA owns 64 recurrent columns.
// GEMM thread tile: 4 rows x 4 cols, K split into 16 chunks of 32.
// Phase-2 weights (Uh slice, 128KB) live permanently in SMEM.
// ---------------------------------------------------------------------------
__global__ void __cluster_dims__(CL, 1, 1) __launch_bounds__(NTH, 1)
rnn_persistent(const float* __restrict__ x,
               const float* __restrict__ W_wz,
               const float* __restrict__ W_wr,
               const float* __restrict__ W_wh,
               float* __restrict__ out_h)
{
    extern __shared__ float dynsm[];
    float (*sUh)[COLS]            = (float (*)[COLS])dynsm;
    float* p = dynsm + NR * COLS;
    float (*sH)[SHP]              = (float (*)[SHP])p;            p += BG * SHP;
    float (*sRed)[NKC][BG][COLS]  = (float (*)[NKC][BG][COLS])p;  p += 2 * NKC * BG * COLS;
    float (*sZ)[COLS]             = (float (*)[COLS])p;           p += BG * COLS;
    float (*sHown)[COLS]          = (float (*)[COLS])p;           p += BG * COLS;
    float (*sWin)[COLS][NIN]      = (float (*)[COLS][NIN])p;      p += 3 * COLS * NIN;
    float (*sX)[NIN]              = (float (*)[NIN])p;

    const int tid     = threadIdx.x;
    const int cta     = blockIdx.x;
    const int cl      = cta / CL;
    const int rank    = cta % CL;
    const int b0      = cl * BG;
    const int colbase = rank * COLS;

    // GEMM thread mapping: warp = one K chunk; lanes span (rowgroup, colgroup).
    const int kc = tid >> 5;              // 0..15
    const int r5 = tid & 31;
    const int j0 = (r5 & 15) << 2;        // 0,4,...,60
    const int rg = (r5 >> 4) << 2;        // 0 or 4 (row base, 4 rows)
    const int kb = kc << 5;               // K chunk base (32 wide)

    // Epilogue mapping: one output element per thread (512 = 8*64).
    const int eb = tid >> 6;              // batch row 0..7
    const int ej = tid & 63;              // column 0..63

    // Load input-projection weight slices (n_in = 2).
    if (tid < COLS) {
        const int j = colbase + tid;
        sWin[0][tid][0] = W_wz[j * NIN + 0];
        sWin[0][tid][1] = W_wz[j * NIN + 1];
        sWin[1][tid][0] = W_wr[j * NIN + 0];
        sWin[1][tid][1] = W_wr[j * NIN + 1];
        sWin[2][tid][0] = W_wh[j * NIN + 0];
        sWin[2][tid][1] = W_wh[j * NIN + 1];
    }

    // Preload the Uh column slice into SMEM (persistent for all 512 steps).
    // sUh[k][j] = g_UhT[k][colbase + j]; 8192 float4 total, 16 per thread.
    for (int i = tid; i < NR * (COLS / 4); i += NTH) {
        const int k = i >> 4, jf = i & 15;
        reinterpret_cast<float4*>(&sUh[k][0])[jf] =
            __ldcg(reinterpret_cast<const float4*>(g_UhT + (size_t)k * NR + colbase) + jf);
    }

    // Load h0 (written by encoder_kernel) into sH.
    for (int i = tid; i < BG * (NR / 4); i += NTH) {
        const int b = i >> 7, idx = i & 127;
        reinterpret_cast<float4*>(&sH[b][0])[idx] =
            __ldcv(reinterpret_cast<const float4*>(g_h + (size_t)(b0 + b) * NR) + idx);
    }
    __syncthreads();

    const float* __restrict__ wzBase = g_UzT + (size_t)kb * NR + colbase + j0;
    const float* __restrict__ wrBase = g_UrT + (size_t)kb * NR + colbase + j0;

    for (int t = 0; t < TT; t++) {
        // Load x_t for our 8 rows.
        if (tid < BG * NIN) {
            const int b = tid >> 1, c = tid & 1;
            sX[b][c] = x[((size_t)(b0 + b) * TT + t) * NIN + c];
        }

        // ---------------- Phase 1: z, r gate GEMMs (weights from L2) --------
        {
            float az[4][4] = {{0,0,0,0},{0,0,0,0},{0,0,0,0},{0,0,0,0}};
            float ar[4][4] = {{0,0,0,0},{0,0,0,0},{0,0,0,0},{0,0,0,0}};
            const float* __restrict__ h0p = &sH[rg + 0][kb];
            const float* __restrict__ h1p = &sH[rg + 1][kb];
            const float* __restrict__ h2p = &sH[rg + 2][kb];
            const float* __restrict__ h3p = &sH[rg + 3][kb];
#pragma unroll 8
            for (int k = 0; k < 32; k++) {
                const float4 wzv = __ldcg(reinterpret_cast<const float4*>(wzBase + (size_t)k * NR));
                const float4 wrv = __ldcg(reinterpret_cast<const float4*>(wrBase + (size_t)k * NR));
                const float hv0 = h0p[k], hv1 = h1p[k], hv2 = h2p[k], hv3 = h3p[k];
                az[0][0] = fmaf(hv0, wzv.x, az[0][0]); az[0][1] = fmaf(hv0, wzv.y, az[0][1]);
                az[0][2] = fmaf(hv0, wzv.z, az[0][2]); az[0][3] = fmaf(hv0, wzv.w, az[0][3]);
                az[1][0] = fmaf(hv1, wzv.x, az[1][0]); az[1][1] = fmaf(hv1, wzv.y, az[1][1]);
                az[1][2] = fmaf(hv1, wzv.z, az[1][2]); az[1][3] = fmaf(hv1, wzv.w, az[1][3]);
                az[2][0] = fmaf(hv2, wzv.x, az[2][0]); az[2][1] = fmaf(hv2, wzv.y, az[2][1]);
                az[2][2] = fmaf(hv2, wzv.z, az[2][2]); az[2][3] = fmaf(hv2, wzv.w, az[2][3]);
                az[3][0] = fmaf(hv3, wzv.x, az[3][0]); az[3][1] = fmaf(hv3, wzv.y, az[3][1]);
                az[3][2] = fmaf(hv3, wzv.z, az[3][2]); az[3][3] = fmaf(hv3, wzv.w, az[3][3]);
                ar[0][0] = fmaf(hv0, wrv.x, ar[0][0]); ar[0][1] = fmaf(hv0, wrv.y, ar[0][1]);
                ar[0][2] = fmaf(hv0, wrv.z, ar[0][2]); ar[0][3] = fmaf(hv0, wrv.w, ar[0][3]);
                ar[1][0] = fmaf(hv1, wrv.x, ar[1][0]); ar[1][1] = fmaf(hv1, wrv.y, ar[1][1]);
                ar[1][2] = fmaf(hv1, wrv.z, ar[1][2]); ar[1][3] = fmaf(hv1, wrv.w, ar[1][3]);
                ar[2][0] = fmaf(hv2, wrv.x, ar[2][0]); ar[2][1] = fmaf(hv2, wrv.y, ar[2][1]);
                ar[2][2] = fmaf(hv2, wrv.z, ar[2][2]); ar[2][3] = fmaf(hv2, wrv.w, ar[2][3]);
                ar[3][0] = fmaf(hv3, wrv.x, ar[3][0]); ar[3][1] = fmaf(hv3, wrv.y, ar[3][1]);
                ar[3][2] = fmaf(hv3, wrv.z, ar[3][2]); ar[3][3] = fmaf(hv3, wrv.w, ar[3][3]);
            }
#pragma unroll
            for (int b = 0; b < 4; b++) {
                *reinterpret_cast<float4*>(&sRed[0][kc][rg + b][j0]) =
                    make_float4(az[b][0], az[b][1], az[b][2], az[b][3]);
                *reinterpret_cast<float4*>(&sRed[1][kc][rg + b][j0]) =
                    make_float4(ar[b][0], ar[b][1], ar[b][2], ar[b][3]);
            }
        }
        __syncthreads();

        // Phase 1 epilogue: reduce chunks, gates, v = r*h (own slice -> g_v).
        {
            float sz = 0.0f, sr = 0.0f;
#pragma unroll
            for (int c = 0; c < NKC; c++) {
                sz += sRed[0][c][eb][ej];
                sr += sRed[1][c][eb][ej];
            }
            const float xz = sX[eb][0] * sWin[0][ej][0] + sX[eb][1] * sWin[0][ej][1];
            const float xr = sX[eb][0] * sWin[1][ej][0] + sX[eb][1] * sWin[1][ej][1];
            const float z  = sigmoidf_(xz + sz);
            const float r  = sigmoidf_(xr + sr);
            const float hc = sH[eb][colbase + ej];
            sZ[eb][ej]    = z;
            sHown[eb][ej] = hc;
            g_v[(size_t)(b0 + eb) * NR + colbase + ej] = r * hc;
        }
        cluster_sync_all();   // all v slices visible cluster-wide

        // Refill sH with full v.
        for (int i = tid; i < BG * (NR / 4); i += NTH) {
            const int b = i >> 7, idx = i & 127;
            reinterpret_cast<float4*>(&sH[b][0])[idx] =
                __ldcv(reinterpret_cast<const float4*>(g_v + (size_t)(b0 + b) * NR) + idx);
        }
        __syncthreads();

        // ---------------- Phase 2: candidate GEMM (weights from SMEM) -------
        {
            float au[4][4] = {{0,0,0,0},{0,0,0,0},{0,0,0,0},{0,0,0,0}};
            const float* __restrict__ v0p = &sH[rg + 0][kb];
            const float* __restrict__ v1p = &sH[rg + 1][kb];
            const float* __restrict__ v2p = &sH[rg + 2][kb];
            const float* __restrict__ v3p = &sH[rg + 3][kb];
#pragma unroll 8
            for (int k = 0; k < 32; k++) {
                const float4 wv = *reinterpret_cast<const float4*>(&sUh[kb + k][j0]);
                const float v0 = v0p[k], v1 = v1p[k], v2 = v2p[k], v3 = v3p[k];
                au[0][0] = fmaf(v0, wv.x, au[0][0]); au[0][1] = fmaf(v0, wv.y, au[0][1]);
                au[0][2] = fmaf(v0, wv.z, au[0][2]); au[0][3] = fmaf(v0, wv.w, au[0][3]);
                au[1][0] = fmaf(v1, wv.x, au[1][0]); au[1][1] = fmaf(v1, wv.y, au[1][1]);
                au[1][2] = fmaf(v1, wv.z, au[1][2]); au[1][3] = fmaf(v1, wv.w, au[1][3]);
                au[2][0] = fmaf(v2, wv.x, au[2][0]); au[2][1] = fmaf(v2, wv.y, au[2][1]);
                au[2][2] = fmaf(v2, wv.z, au[2][2]); au[2][3] = fmaf(v2, wv.w, au[2][3]);
                au[3][0] = fmaf(v3, wv.x, au[3][0]); au[3][1] = fmaf(v3, wv.y, au[3][1]);
                au[3][2] = fmaf(v3, wv.z, au[3][2]); au[3][3] = fmaf(v3, wv.w, au[3][3]);
            }
#pragma unroll
            for (int b = 0; b < 4; b++)
                *reinterpret_cast<float4*>(&sRed[0][kc][rg + b][j0]) =
                    make_float4(au[b][0], au[b][1], au[b][2], au[b][3]);
        }
        __syncthreads();

        // Phase 2 epilogue: u, tanh, leaky update; write h_t to output + g_h.
        {
            float su = 0.0f;
#pragma unroll
            for (int c = 0; c < NKC; c++)
                su += sRed[0][c][eb][ej];
            const float xh = sX[eb][0] * sWin[2][ej][0] + sX[eb][1] * sWin[2][ej][1];
            const float u  = xh + su;
            const float hc = sHown[eb][ej];
            const float z  = sZ[eb][ej];
            const float hn = hc + DTAU * (z - 1.0f) * (hc - tanhf(u));
            out_h[((size_t)(b0 + eb) * TT + t) * NR + colbase + ej] = hn;
            g_h[(size_t)(b0 + eb) * NR + colbase + ej] = hn;
        }
        cluster_sync_all();   // all new-h slices visible cluster-wide

        // Refill sH with full new h for next step.
        for (int i = tid; i < BG * (NR / 4); i += NTH) {
            const int b = i >> 7, idx = i & 127;
            reinterpret_cast<float4*>(&sH[b][0])[idx] =
                __ldcv(reinterpret_cast<const float4*>(g_h + (size_t)(b0 + b) * NR) + idx);
        }
        __syncthreads();
    }
}

// ---------------------------------------------------------------------------
// Decoder GEMM: y[bt][o] = sum_r h[bt][r] * W_dec[o][r]
//             = A (65536 x 512) * g_WdT (512 x 512)
// 128x128 block tile, K-tile 8, 8x8 thread tile (2x2 quadrants of 4).
// grid (4, 512), 256 threads.
// ---------------------------------------------------------------------------
__global__ void __launch_bounds__(256)
decoder_gemm(const float* __restrict__ A, float* __restrict__ C) {
    __shared__ float As[8][128];
    __shared__ float Bs[8][128];

    const int tid = threadIdx.x;
    const int tx = tid & 15;       // 16
    const int ty = tid >> 4;       // 16
    const int m0 = blockIdx.y * 128;
    const int n0 = blockIdx.x * 128;

    float acc[8][8];
#pragma unroll
    for (int i = 0; i < 8; i++)
#pragma unroll
        for (int j = 0; j < 8; j++) acc[i][j] = 0.0f;

    const int lrow = tid >> 1;          // 0..127
    const int lk   = (tid & 1) << 2;    // 0 or 4
    const int brow = tid >> 5;          // 0..7
    const int bcol = (tid & 31) << 2;   // 0..124

    for (int k0 = 0; k0 < NR; k0 += 8) {
        const float4 av = *reinterpret_cast<const float4*>(
            A + (size_t)(m0 + lrow) * NR + k0 + lk);
        As[lk + 0][lrow] = av.x;
        As[lk + 1][lrow] = av.y;
        As[lk + 2][lrow] = av.z;
        As[lk + 3][lrow] = av.w;
        *reinterpret_cast<float4*>(&Bs[brow][bcol]) =
            *reinterpret_cast<const float4*>(
                g_WdT + (size_t)(k0 + brow) * NR + n0 + bcol);
        __syncthreads();

#pragma unroll
        for (int kk = 0; kk < 8; kk++) {
            float a[8], b[8];
            *reinterpret_cast<float4*>(a)     = *reinterpret_cast<const float4*>(&As[kk][ty * 4]);
            *reinterpret_cast<float4*>(a + 4) = *reinterpret_cast<const float4*>(&As[kk][64 + ty * 4]);
            *reinterpret_cast<float4*>(b)     = *reinterpret_cast<const float4*>(&Bs[kk][tx * 4]);
            *reinterpret_cast<float4*>(b + 4) = *reinterpret_cast<const float4*>(&Bs[kk][64 + tx * 4]);
#pragma unroll
            for (int i = 0; i < 8; i++)
#pragma unroll
                for (int j = 0; j < 8; j++)
                    acc[i][j] = fmaf(a[i], b[j], acc[i][j]);
        }
        __syncthreads();
    }

#pragma unroll
    for (int ri = 0; ri < 2; ri++) {
#pragma unroll
        for (int i = 0; i < 4; i++) {
            const int row = m0 + ri * 64 + ty * 4 + i;
            const int ii = ri * 4 + i;
            *reinterpret_cast<float4*>(C + (size_t)row * NR + n0 + tx * 4) =
                make_float4(acc[ii][0], acc[ii][1], acc[ii][2], acc[ii][3]);
            *reinterpret_cast<float4*>(C + (size_t)row * NR + n0 + 64 + tx * 4) =
                make_float4(acc[ii][4], acc[ii][5], acc[ii][6], acc[ii][7]);
        }
    }
}

// ---------------------------------------------------------------------------
// Launch. Inputs (metadata order): x, init_state, W_enc, W_wz, W_uz, W_wr,
// W_ur, W_wh, W_uh, W_dec. Output: [h_1t | y_1t] concatenated,
// each (B, T, NR) fp32.
// ---------------------------------------------------------------------------
extern "C" void kernel_launch(void* const* d_in, const int* in_sizes, int n_in,
                              void* d_out, int out_size) {
    const float* x     = (const float*)d_in[0];
    const float* init  = (const float*)d_in[1];
    const float* W_enc = (const float*)d_in[2];
    const float* W_wz  = (const float*)d_in[3];
    const float* W_uz  = (const float*)d_in[4];
    const float* W_wr  = (const float*)d_in[5];
    const float* W_ur  = (const float*)d_in[6];
    const float* W_wh  = (const float*)d_in[7];
    const float* W_uh  = (const float*)d_in[8];
    const float* W_dec = (const float*)d_in[9];

    float* out_h = (float*)d_out;
    float* out_y = out_h + (size_t)BN * TT * NR;

    cudaFuncSetAttribute(rnn_persistent,
                         cudaFuncAttributeMaxDynamicSharedMemorySize, SM_BYTES);

    transpose_all<<<dim3(16, 16, 5), dim3(32, 8)>>>(W_uz, W_ur, W_uh, W_enc, W_dec);
    encoder_kernel<<<dim3(BN, 4), 128>>>(init);
    rnn_persistent<<<BN, NTH, SM_BYTES>>>(x, W_wz, W_wr, W_wh, out_h);
    decoder_gemm<<<dim3(4, 512), 256>>>(out_h, out_y);
}